// round 11
// baseline (speedup 1.0000x reference)
#include <cuda_runtime.h>
#include <cuda_bf16.h>

#define FULL 0xffffffffu

struct C2 { float x, y; };
__device__ __forceinline__ C2 mkc(float x, float y){ C2 c; c.x=x; c.y=y; return c; }
#define DUP(s) mkc((s),(s))

// ---------- packed f32x2 elementwise ops ----------
__device__ __forceinline__ C2 pfma(C2 a, C2 b, C2 c){
    C2 r;
    asm("{\n\t.reg .b64 A,B,C,D;\n\t"
        "mov.b64 A,{%2,%3};\n\t"
        "mov.b64 B,{%4,%5};\n\t"
        "mov.b64 C,{%6,%7};\n\t"
        "fma.rn.f32x2 D, A, B, C;\n\t"
        "mov.b64 {%0,%1}, D;\n\t}"
        : "=f"(r.x), "=f"(r.y)
        : "f"(a.x), "f"(a.y), "f"(b.x), "f"(b.y), "f"(c.x), "f"(c.y));
    return r;
}
__device__ __forceinline__ C2 pmul(C2 a, C2 b){
    C2 r;
    asm("{\n\t.reg .b64 A,B,D;\n\t"
        "mov.b64 A,{%2,%3};\n\t"
        "mov.b64 B,{%4,%5};\n\t"
        "mul.rn.f32x2 D, A, B;\n\t"
        "mov.b64 {%0,%1}, D;\n\t}"
        : "=f"(r.x), "=f"(r.y)
        : "f"(a.x), "f"(a.y), "f"(b.x), "f"(b.y));
    return r;
}
__device__ __forceinline__ C2 swapc(C2 v){ return mkc(v.y, v.x); }
__device__ __forceinline__ C2 cmul_s(C2 a, C2 b){
    return mkc(a.x*b.x - a.y*b.y, a.x*b.y + a.y*b.x);
}
__device__ __forceinline__ constexpr int cpop(int v){
    return (v&1)+((v>>1)&1)+((v>>2)&1);
}
// a * w (complex), packed
__device__ __forceinline__ C2 capply(C2 a, C2 w){
    return pfma(mkc(-w.y, w.y), swapc(a), pmul(DUP(w.x), a));
}

// ============================================================================
// Mapping: 8 amplitudes/thread (k bits 0..2), 32 lanes/element, 1 elem/warp.
//   q7->k1, q5->k2, q3->k4  (LOCAL)
//   q6->l1, q4->l2, q2->l4, q0->l8, q1->l16  (LANE)
// ============================================================================

// ---- per-k compile-time diag: multiply a[k] by i^((popc(k&MP)+3*popc(k&MM))&3)
template<int MP, int MM>
__device__ __forceinline__ void kdiag8(C2 a[8]){
    #pragma unroll
    for (int k = 0; k < 8; ++k){
        const int e = (cpop(k & MP) + 3 * cpop(k & MM)) & 3;
        if (e == 1){ float t = a[k].x; a[k].x = -a[k].y; a[k].y =  t; }
        else if (e == 2){ a[k].x = -a[k].x; a[k].y = -a[k].y; }
        else if (e == 3){ float t = a[k].x; a[k].x =  a[k].y; a[k].y = -t; }
    }
}

__device__ __forceinline__ void diag_all8(C2 a[8], C2 W){
    C2 P = DUP(W.x), Q = mkc(-W.y, W.y);
    #pragma unroll
    for (int k = 0; k < 8; ++k)
        a[k] = pfma(Q, swapc(a[k]), pmul(P, a[k]));
}

// multiply all regs by W where cb, else identity
__device__ __forceinline__ void diag_cond8(C2 a[8], C2 W, bool cb){
    C2 P = DUP(cb ? W.x : 1.0f);
    C2 Q = cb ? mkc(-W.y, W.y) : DUP(0.f);
    #pragma unroll
    for (int k = 0; k < 8; ++k)
        a[k] = pfma(Q, swapc(a[k]), pmul(P, a[k]));
}

// multiply all regs by i where cb
__device__ __forceinline__ void mul_i_sel8(C2 a[8], bool cb){
    #pragma unroll
    for (int k = 0; k < 8; ++k){
        float nx = cb ? -a[k].y : a[k].x;
        float ny = cb ?  a[k].x : a[k].y;
        a[k].x = nx; a[k].y = ny;
    }
}

// multiply a[k] by w1^popc(k&MASK)  (popc <= 2)
template<int MASK>
__device__ __forceinline__ void zpow8(C2 a[8], C2 w1, C2 w2){
    #pragma unroll
    for (int k = 0; k < 8; ++k){
        const int p = cpop(k & MASK);
        if (p) a[k] = capply(a[k], (p == 1) ? w1 : w2);
    }
}

// local RY on k bit M
template<int M>
__device__ __forceinline__ void ry_loc8(C2 a[8], float c, float s){
    C2 c2 = DUP(c), s2 = DUP(s), ns2 = DUP(-s);
    #pragma unroll
    for (int k0 = 0; k0 < 8; ++k0) if (!(k0 & M)){
        int k1 = k0 | M;
        C2 a0 = a[k0], a1 = a[k1];
        a[k0] = pfma(c2, a0, pmul(ns2, a1));
        a[k1] = pfma(s2, a0, pmul(c2, a1));
    }
}

// X on local bit M if cb
template<int M>
__device__ __forceinline__ void xsel_loc8(C2 a[8], bool cb){
    #pragma unroll
    for (int k0 = 0; k0 < 8; ++k0) if (!(k0 & M)){
        int k1 = k0 | M;
        C2 t0 = a[k0], t1 = a[k1];
        a[k0] = cb ? t1 : t0;
        a[k1] = cb ? t0 : t1;
    }
}

// compile-time local CX: control bit MC, target bit MT
template<int MC, int MT>
__device__ __forceinline__ void cx_loc8(C2 a[8]){
    #pragma unroll
    for (int k0 = 0; k0 < 8; ++k0) if ((k0 & MC) && !(k0 & MT)){
        int k1 = k0 | MT; C2 t = a[k0]; a[k0] = a[k1]; a[k1] = t;
    }
}

// merged CX stage for pairs (2,3),(4,5),(6,7): reg k shuffles by lane mask k
__device__ __forceinline__ void cx_shfl_k8(C2 a[8]){
    #pragma unroll
    for (int k = 1; k < 8; ++k){
        a[k].x = __shfl_xor_sync(FULL, a[k].x, k);
        a[k].y = __shfl_xor_sync(FULL, a[k].y, k);
    }
}

// conditional lane X: all regs exchanged across lane bit MT where cb
template<int MT>
__device__ __forceinline__ void cxl_lane8(C2 a[8], bool cb){
    #pragma unroll
    for (int k = 0; k < 8; ++k){
        float px = __shfl_xor_sync(FULL, a[k].x, MT);
        float py = __shfl_xor_sync(FULL, a[k].y, MT);
        a[k].x = cb ? px : a[k].x;
        a[k].y = cb ? py : a[k].y;
    }
}

// local-ctrl lane-tgt CX (complex): regs with k&MC shuffle by MT
template<int MC, int MT>
__device__ __forceinline__ void cx_cl8(C2 a[8]){
    #pragma unroll
    for (int k = 0; k < 8; ++k) if (k & MC){
        a[k].x = __shfl_xor_sync(FULL, a[k].x, MT);
        a[k].y = __shfl_xor_sync(FULL, a[k].y, MT);
    }
}

// fused RY(theta_eff)·(X if cb) on LANE bit LM; cb runtime (lane-bit control).
// cb=0: RY(t1+t2) -> (cs_,ss_); cb=1: X·RY(t1-t2) -> (cd_,sd_).
template<int LM>
__device__ __forceinline__ void ry_lane_fx8(C2 a[8], bool cb,
        float cs_, float ss_, float cd_, float sd_, int lane){
    bool hi = (lane & LM) != 0;
    float ca = cb ? (hi ? -sd_ : sd_) : cs_;
    float co = cb ? cd_ : (hi ? ss_ : -ss_);
    C2 CA = DUP(ca), CO = DUP(co);
    #pragma unroll
    for (int k = 0; k < 8; ++k){
        float px = __shfl_xor_sync(FULL, a[k].x, LM);
        float py = __shfl_xor_sync(FULL, a[k].y, LM);
        a[k] = pfma(CA, a[k], pmul(CO, mkc(px, py)));
    }
}

// fused RY·(X if k&KM) on LANE bit LM; control is LOCAL bit KM (compile-time per reg)
template<int LM, int KM>
__device__ __forceinline__ void ry_lane_fxk8(C2 a[8],
        float cs_, float ss_, float cd_, float sd_, int lane){
    bool hi = (lane & LM) != 0;
    C2 CA0 = DUP(cs_),              CO0 = DUP(hi ? ss_ : -ss_);
    C2 CA1 = DUP(hi ? -sd_ : sd_),  CO1 = DUP(cd_);
    #pragma unroll
    for (int k = 0; k < 8; ++k){
        float px = __shfl_xor_sync(FULL, a[k].x, LM);
        float py = __shfl_xor_sync(FULL, a[k].y, LM);
        if (k & KM) a[k] = pfma(CA1, a[k], pmul(CO1, mkc(px, py)));
        else        a[k] = pfma(CA0, a[k], pmul(CO0, mkc(px, py)));
    }
}

// fused RY·(cond X) on LOCAL bit M with runtime cb (lane-bit control)
template<int M>
__device__ __forceinline__ void ry_loc_fx8(C2 a[8], bool cb,
        float cs_, float ss_, float cd_, float sd_){
    float ce = cb ? cd_ : cs_;
    float se = cb ? sd_ : ss_;
    ry_loc8<M>(a, ce, se);
    xsel_loc8<M>(a, cb);
}

// fused RY·(X if k&KM) on LOCAL bit MT; control LOCAL bit KM (compile-time)
template<int KM, int MT>
__device__ __forceinline__ void ry_loc_sel_x8(C2 a[8],
        float cs_, float ss_, float cd_, float sd_){
    #pragma unroll
    for (int k0 = 0; k0 < 8; ++k0) if (!(k0 & MT)){
        int k1 = k0 | MT;
        const float ce = (k0 & KM) ? cd_ : cs_;
        const float se = (k0 & KM) ? sd_ : ss_;
        C2 a0 = a[k0], a1 = a[k1];
        C2 n0 = pfma(DUP(ce), a0, pmul(DUP(-se), a1));
        C2 n1 = pfma(DUP(se), a0, pmul(DUP(ce), a1));
        if (k0 & KM){ a[k0] = n1; a[k1] = n0; }
        else        { a[k0] = n0; a[k1] = n1; }
    }
}

// ---------------- generic complex 1q gate ----------------
template<int M>
__device__ __forceinline__ void g1_loc8(C2 a[8], C2 u00, C2 u01, C2 u10, C2 u11){
    C2 x00 = DUP(u00.x), y00 = mkc(-u00.y, u00.y);
    C2 x01 = DUP(u01.x), y01 = mkc(-u01.y, u01.y);
    C2 x10 = DUP(u10.x), y10 = mkc(-u10.y, u10.y);
    C2 x11 = DUP(u11.x), y11 = mkc(-u11.y, u11.y);
    #pragma unroll
    for (int k0 = 0; k0 < 8; ++k0) if (!(k0 & M)){
        int k1 = k0 | M;
        C2 a0 = a[k0], a1 = a[k1];
        C2 a0s = swapc(a0), a1s = swapc(a1);
        C2 t0 = pmul(x00, a0); t0 = pfma(y00, a0s, t0);
        t0 = pfma(x01, a1, t0); t0 = pfma(y01, a1s, t0);
        C2 t1 = pmul(x10, a0); t1 = pfma(y10, a0s, t1);
        t1 = pfma(x11, a1, t1); t1 = pfma(y11, a1s, t1);
        a[k0] = t0; a[k1] = t1;
    }
}

template<int LM>
__device__ __forceinline__ void g1_lane8(C2 a[8], C2 u00, C2 u01, C2 u10, C2 u11, int lane){
    bool hi = (lane & LM) != 0;
    C2 xA = hi ? DUP(u11.x) : DUP(u00.x);
    C2 yA = hi ? mkc(-u11.y, u11.y) : mkc(-u00.y, u00.y);
    C2 xB = hi ? DUP(u10.x) : DUP(u01.x);
    C2 yB = hi ? mkc(-u10.y, u10.y) : mkc(-u01.y, u01.y);
    #pragma unroll
    for (int k = 0; k < 8; ++k){
        float px = __shfl_xor_sync(FULL, a[k].x, LM);
        float py = __shfl_xor_sync(FULL, a[k].y, LM);
        C2 t = pmul(xA, a[k]); t = pfma(yA, swapc(a[k]), t);
        t = pfma(xB, mkc(px, py), t); t = pfma(yB, mkc(py, px), t);
        a[k] = t;
    }
}

// ---------------- CRX variants ----------------
// local-local
template<int MC, int MT>
__device__ __forceinline__ void gcrx_loc8(C2 a[8], float c, float s){
    C2 c2 = DUP(c), sn = mkc(s, -s);
    #pragma unroll
    for (int k0 = 0; k0 < 8; ++k0) if ((k0 & MC) && !(k0 & MT)){
        int k1 = k0 | MT;
        C2 a0 = a[k0], a1 = a[k1];
        a[k0] = pfma(c2, a0, pmul(sn, swapc(a1)));
        a[k1] = pfma(c2, a1, pmul(sn, swapc(a0)));
    }
}
// lane ctrl (cb), local tgt
template<int MT>
__device__ __forceinline__ void gcrx_lt8(C2 a[8], bool cb, float c, float s){
    C2 c2 = DUP(cb ? c : 1.0f);
    C2 sn = cb ? mkc(s, -s) : DUP(0.f);
    #pragma unroll
    for (int k0 = 0; k0 < 8; ++k0) if (!(k0 & MT)){
        int k1 = k0 | MT;
        C2 a0 = a[k0], a1 = a[k1];
        a[k0] = pfma(c2, a0, pmul(sn, swapc(a1)));
        a[k1] = pfma(c2, a1, pmul(sn, swapc(a0)));
    }
}
// local ctrl (k&MC), lane tgt
template<int MC, int MT>
__device__ __forceinline__ void gcrx_cl8(C2 a[8], float c, float s){
    C2 c2 = DUP(c), sn = mkc(s, -s);
    #pragma unroll
    for (int k = 0; k < 8; ++k) if (k & MC){
        float px = __shfl_xor_sync(FULL, a[k].x, MT);
        float py = __shfl_xor_sync(FULL, a[k].y, MT);
        a[k] = pfma(c2, a[k], pmul(sn, mkc(py, px)));
    }
}
// lane-lane: ctrl cb, tgt lane bit MT
template<int MT>
__device__ __forceinline__ void gcrx_ll8(C2 a[8], bool cb, float c, float s){
    C2 c2 = DUP(cb ? c : 1.0f);
    C2 sn = cb ? mkc(s, -s) : DUP(0.f);
    #pragma unroll
    for (int k = 0; k < 8; ++k){
        float px = __shfl_xor_sync(FULL, a[k].x, MT);
        float py = __shfl_xor_sync(FULL, a[k].y, MT);
        a[k] = pfma(c2, a[k], pmul(sn, mkc(py, px)));
    }
}

// ---------------- real-state encode gates ----------------
template<int M>
__device__ __forceinline__ void gryR_loc8(float r[8], float c, float s){
    C2 c2 = DUP(c);
    if constexpr (M == 1){
        C2 snn = mkc(-s, s);
        #pragma unroll
        for (int j = 0; j < 4; ++j){
            C2 v = mkc(r[2*j], r[2*j+1]);
            C2 res = pfma(snn, swapc(v), pmul(c2, v));
            r[2*j] = res.x; r[2*j+1] = res.y;
        }
    } else {
        constexpr int pm = M >> 1;  // pair index bit (pairs of adjacent floats)
        C2 s2 = DUP(s), ns2 = DUP(-s);
        #pragma unroll
        for (int j0 = 0; j0 < 4; ++j0) if (!(j0 & pm)){
            int j1 = j0 | pm;
            C2 v0 = mkc(r[2*j0], r[2*j0+1]);
            C2 v1 = mkc(r[2*j1], r[2*j1+1]);
            C2 n0 = pfma(c2, v0, pmul(ns2, v1));
            C2 n1 = pfma(s2, v0, pmul(c2, v1));
            r[2*j0] = n0.x; r[2*j0+1] = n0.y;
            r[2*j1] = n1.x; r[2*j1+1] = n1.y;
        }
    }
}
template<int LM>
__device__ __forceinline__ void gryR_lane8(float r[8], float c, float s, int lane){
    C2 c2 = DUP(c);
    C2 sg2 = (lane & LM) ? DUP(s) : DUP(-s);
    #pragma unroll
    for (int j = 0; j < 4; ++j){
        float px = __shfl_xor_sync(FULL, r[2*j],   LM);
        float py = __shfl_xor_sync(FULL, r[2*j+1], LM);
        C2 v = mkc(r[2*j], r[2*j+1]);
        C2 res = pfma(c2, v, pmul(sg2, mkc(px, py)));
        r[2*j] = res.x; r[2*j+1] = res.y;
    }
}
// CX real: lane-lane
template<int MT>
__device__ __forceinline__ void gcxR_ll8(float r[8], bool cb){
    #pragma unroll
    for (int j = 0; j < 8; ++j){
        float pv = __shfl_xor_sync(FULL, r[j], MT);
        r[j] = cb ? pv : r[j];
    }
}
// CX real: lane ctrl, local tgt
template<int MT>
__device__ __forceinline__ void gcxR_lt8(float r[8], bool cb){
    #pragma unroll
    for (int j0 = 0; j0 < 8; ++j0) if (!(j0 & MT)){
        int j1 = j0 | MT;
        float t0 = r[j0], t1 = r[j1];
        r[j0] = cb ? t1 : t0;
        r[j1] = cb ? t0 : t1;
    }
}
// CX real: local ctrl, lane tgt
template<int MC, int MT>
__device__ __forceinline__ void gcxR_cl8(float r[8]){
    #pragma unroll
    for (int j = 0; j < 8; ++j) if (j & MC)
        r[j] = __shfl_xor_sync(FULL, r[j], MT);
}

__device__ __forceinline__ float wsum32(float v){
    #pragma unroll
    for (int o = 16; o; o >>= 1) v += __shfl_xor_sync(FULL, v, o);
    return v;
}

__device__ __forceinline__ void u3r(float t, float ph, float la,
                                    C2& U00, C2& U01, C2& U10, C2& U11){
    float st, ct, sp, cp, sl, cl, spl, cpl;
    __sincosf(t * 0.5f, &st, &ct);
    __sincosf(ph, &sp, &cp);
    __sincosf(la, &sl, &cl);
    __sincosf(ph + la, &spl, &cpl);
    U00 = mkc(ct, 0.f);
    U01 = mkc(-cl*st, -sl*st);
    U10 = mkc( cp*st,  sp*st);
    U11 = mkc(cpl*ct, spl*ct);
}

__global__ void __launch_bounds__(128, 10)
qcnn_kernel(const float* __restrict__ x,
            const float* __restrict__ rz_p,  const float* __restrict__ ry_p,
            const float* __restrict__ ry2_p, const float* __restrict__ crx_p,
            const float* __restrict__ u3_p,  const float* __restrict__ u3b_p,
            const float* __restrict__ W1,    const float* __restrict__ b1,
            const float* __restrict__ W2,    const float* __restrict__ b2,
            float* __restrict__ out, int B)
{
    const int elem = (blockIdx.x * blockDim.x + threadIdx.x) >> 5;
    const int lane = threadIdx.x & 31;
    if (elem >= B) return;

    // ================= encode (state purely REAL) =================
    float ang = __ldg(x + elem * 32 + lane);   // 32 angles = one per lane
    float myc, mys;
    __sincosf(0.5f * ang, &mys, &myc);

    float r[8];
    #pragma unroll
    for (int k = 0; k < 8; ++k) r[k] = 0.0f;
    r[0] = (lane == 0) ? 1.0f : 0.0f;

    #define RYQE(CY,Q,GATE) do { \
        float cc_ = __shfl_sync(FULL, myc, (CY)*8 + (Q)); \
        float ss_ = __shfl_sync(FULL, mys, (CY)*8 + (Q)); \
        GATE; } while(0)

    #define ENC_CYC(CY) \
        RYQE(CY,0, (gryR_lane8<8>(r, cc_, ss_, lane)));  \
        RYQE(CY,1, (gryR_lane8<16>(r, cc_, ss_, lane))); \
        RYQE(CY,2, (gryR_lane8<4>(r, cc_, ss_, lane)));  \
        RYQE(CY,3, (gryR_loc8<4>(r, cc_, ss_)));         \
        RYQE(CY,4, (gryR_lane8<2>(r, cc_, ss_, lane)));  \
        RYQE(CY,5, (gryR_loc8<2>(r, cc_, ss_)));         \
        RYQE(CY,6, (gryR_lane8<1>(r, cc_, ss_, lane)));  \
        RYQE(CY,7, (gryR_loc8<1>(r, cc_, ss_)));         \
        gcxR_ll8<16>(r, (lane & 8)  != 0);  /* CX(0,1) */ \
        gcxR_ll8<4>(r,  (lane & 16) != 0);  /* CX(1,2) */ \
        gcxR_lt8<4>(r,  (lane & 4)  != 0);  /* CX(2,3) */ \
        gcxR_cl8<4,2>(r);                   /* CX(3,4) */ \
        gcxR_lt8<2>(r,  (lane & 2)  != 0);  /* CX(4,5) */ \
        gcxR_cl8<2,1>(r);                   /* CX(5,6) */ \
        gcxR_lt8<1>(r,  (lane & 1)  != 0);  /* CX(6,7) */ \
        gcxR_cl8<1,8>(r);                   /* CX(7,0) */

    ENC_CYC(0) ENC_CYC(1) ENC_CYC(2) ENC_CYC(3)

    // ================= psi1 FIRST =================
    C2 a[8];
    #pragma unroll
    for (int k = 0; k < 8; ++k) a[k] = mkc(r[k], 0.f);

    {   // layer 0
        float xc, xs;
        __sincosf(__ldg(crx_p) * 0.5f, &xs, &xc);
        gcrx_ll8<16>(a, (lane & 8) != 0, xc, xs);   // (0,1): ctrl l8, tgt l16
        gcrx_lt8<4>(a,  (lane & 4) != 0, xc, xs);   // (2,3): ctrl l4, tgt k4
        gcrx_lt8<2>(a,  (lane & 2) != 0, xc, xs);   // (4,5)
        gcrx_lt8<1>(a,  (lane & 1) != 0, xc, xs);   // (6,7)
        gcrx_ll8<4>(a,  (lane & 16) != 0, xc, xs);  // (1,2): ctrl l16, tgt l4
        gcrx_cl8<4,2>(a, xc, xs);                   // (3,4): ctrl k4, tgt l2
        gcrx_cl8<2,1>(a, xc, xs);                   // (5,6): ctrl k2, tgt l1
        C2 U00, U01, U10, U11;
        u3r(__ldg(u3b_p), __ldg(u3b_p+1), __ldg(u3b_p+2), U00, U01, U10, U11);
        g1_lane8<16>(a, U00, U01, U10, U11, lane);  // q1
        g1_loc8<4>(a, U00, U01, U10, U11);          // q3
        g1_loc8<2>(a, U00, U01, U10, U11);          // q5
        g1_loc8<1>(a, U00, U01, U10, U11);          // q7
    }
    {   // layer 1
        float xc, xs;
        __sincosf(__ldg(crx_p+1) * 0.5f, &xs, &xc);
        gcrx_lt8<4>(a, (lane & 16) != 0, xc, xs);   // (1,3): ctrl l16, tgt k4
        gcrx_loc8<2,1>(a, xc, xs);                  // (5,7): ctrl k2, tgt k1
        gcrx_loc8<4,2>(a, xc, xs);                  // (3,5): ctrl k4, tgt k2
        C2 U00, U01, U10, U11;
        u3r(__ldg(u3b_p+3), __ldg(u3b_p+4), __ldg(u3b_p+5), U00, U01, U10, U11);
        g1_loc8<4>(a, U00, U01, U10, U11);          // q3
        g1_loc8<1>(a, U00, U01, U10, U11);          // q7
    }

    float f2, f3;
    {
        float p3 = 0.f, p7 = 0.f;
        #pragma unroll
        for (int k = 0; k < 8; ++k){
            float m = fmaf(a[k].x, a[k].x, a[k].y * a[k].y);
            p3 += (k & 4) ? -m : m;
            p7 += (k & 1) ? -m : m;
        }
        f2 = wsum32(p3);
        f3 = wsum32(p7);
    }

    // ================= psi0 =================
    #pragma unroll
    for (int k = 0; k < 8; ++k) a[k] = mkc(r[k], 0.f);

    {   // ---- layer 0 ----
        float zs, zc;
        __sincosf(__ldg(rz_p), &zs, &zc);
        C2 w1 = mkc(zc, zs);
        C2 w2 = cmul_s(w1, w1);
        float yc, ys, y2c, y2s;
        __sincosf(__ldg(ry_p)  * 0.5f, &ys,  &yc);
        __sincosf(__ldg(ry2_p) * 0.5f, &y2s, &y2c);
        const float cs_ = yc*y2c - ys*y2s, ss_ = ys*y2c + yc*y2s;   // t1+t2
        const float cd_ = yc*y2c + ys*y2s, sd_ = ys*y2c - yc*y2s;   // t1-t2

        // grand per-lane diag: W = w1^popc(lane&15) * (lane&16 ? -i : 1)
        C2 W;
        {
            int p = __popc((unsigned)(lane & 15));
            W = (p & 1) ? w1 : mkc(1.f, 0.f);
            if (p & 2) W = cmul_s(W, w2);
            if (p & 4) W = cmul_s(W, cmul_s(w2, w2));
            if (lane & 16) W = mkc(W.y, -W.x);   // * (-i)
        }

        // ---- parity-0: pairs (0,1),(2,3),(4,5),(6,7) ----
        kdiag8<0, 7>(a);                       // (-i)^popc(k&7) on q3,q5,q7
        cx_shfl_k8(a);                         // CX(qt,qc) for (2,3),(4,5),(6,7)
        cxl_lane8<8>(a, (lane & 16) != 0);     // CX(q1->q0)
        diag_all8(a, W);                       // merged RZ step (incl. q1's -i)
        {   // fused RY·CX·RY
            ry_loc_fx8<4>(a, (lane & 4) != 0, cs_, ss_, cd_, sd_);   // (2,3)
            ry_loc_fx8<2>(a, (lane & 2) != 0, cs_, ss_, cd_, sd_);   // (4,5)
            ry_loc_fx8<1>(a, (lane & 1) != 0, cs_, ss_, cd_, sd_);   // (6,7)
            ry_lane_fx8<16>(a, (lane & 8) != 0, cs_, ss_, cd_, sd_, lane); // (0,1)
        }
        cx_shfl_k8(a);                         // gate-7
        cxl_lane8<8>(a, (lane & 16) != 0);
        mul_i_sel8(a, (lane & 8) != 0);        // gate-8 merged w/ parity-1 gate-1

        // ---- parity-1: pairs (1,2),(3,4),(5,6) ----
        cxl_lane8<16>(a, (lane & 4) != 0);     // (1,2): ctrl l4, tgt l16
        xsel_loc8<4>(a, (lane & 2) != 0);      // (3,4): ctrl l2, tgt k4
        xsel_loc8<2>(a, (lane & 1) != 0);      // (5,6): ctrl l1, tgt k2
        zpow8<6>(a, w1, w2);                   // RZ on q3(k4),q5(k2)
        diag_cond8(a, w1, (lane & 16) != 0);   // RZ on q1(l16)
        ry_lane_fx8<4>(a, (lane & 16) != 0, cs_, ss_, cd_, sd_, lane); // (1,2)
        ry_lane_fxk8<2, 4>(a, cs_, ss_, cd_, sd_, lane);               // (3,4)
        ry_lane_fxk8<1, 2>(a, cs_, ss_, cd_, sd_, lane);               // (5,6)
        cxl_lane8<16>(a, (lane & 4) != 0);     // gate-7
        xsel_loc8<4>(a, (lane & 2) != 0);
        xsel_loc8<2>(a, (lane & 1) != 0);
        kdiag8<6, 0>(a);                       // gate-8: i^popc(k&6)
        mul_i_sel8(a, (lane & 16) != 0);       //          i^b16

        C2 U00, U01, U10, U11;
        u3r(__ldg(u3_p), __ldg(u3_p+1), __ldg(u3_p+2), U00, U01, U10, U11);
        g1_lane8<16>(a, U00, U01, U10, U11, lane);  // q1
        g1_loc8<4>(a, U00, U01, U10, U11);          // q3
        g1_loc8<2>(a, U00, U01, U10, U11);          // q5
        g1_loc8<1>(a, U00, U01, U10, U11);          // q7
    }

    {   // ---- layer 1: pairs (1,3),(5,7) then (3,5) ----
        float zs, zc;
        __sincosf(__ldg(rz_p+1), &zs, &zc);
        C2 w1 = mkc(zc, zs);
        float yc, ys, y2c, y2s;
        __sincosf(__ldg(ry_p+1)  * 0.5f, &ys,  &yc);
        __sincosf(__ldg(ry2_p+1) * 0.5f, &y2s, &y2c);
        const float cs_ = yc*y2c - ys*y2s, ss_ = ys*y2c + yc*y2s;
        const float cd_ = yc*y2c + ys*y2s, sd_ = ys*y2c - yc*y2s;

        // parity-0
        kdiag8<0, 5>(a);                       // (-i) on q3(k4), q7(k1)
        cx_cl8<4, 16>(a);                      // (1,3): ctrl k4, tgt l16
        cx_loc8<1, 2>(a);                      // (5,7): ctrl k1, tgt k2
        zpow8<2>(a, w1, w1);                   // RZ q5 (exp<=1)
        diag_cond8(a, w1, (lane & 16) != 0);   // RZ q1
        ry_loc_fx8<4>(a, (lane & 16) != 0, cs_, ss_, cd_, sd_);  // (1,3)
        ry_loc_sel_x8<2, 1>(a, cs_, ss_, cd_, sd_);              // (5,7)
        cx_cl8<4, 16>(a);                      // gate-7
        cx_loc8<1, 2>(a);
        mul_i_sel8(a, (lane & 16) != 0);       // gate-8 merged (k2 phases cancel)

        // parity-1: (3,5)
        cx_loc8<2, 4>(a);                      // ctrl q5(k2), tgt q3(k4)
        zpow8<4>(a, w1, w1);                   // RZ q3 (exp<=1)
        ry_loc_sel_x8<4, 2>(a, cs_, ss_, cd_, sd_);
        cx_loc8<2, 4>(a);
        kdiag8<4, 0>(a);                       // i^[k4]

        C2 U00, U01, U10, U11;
        u3r(__ldg(u3_p+3), __ldg(u3_p+4), __ldg(u3_p+5), U00, U01, U10, U11);
        g1_loc8<4>(a, U00, U01, U10, U11);     // q3
        g1_loc8<1>(a, U00, U01, U10, U11);     // q7
    }

    float f0, f1;
    {
        float p3 = 0.f, p7 = 0.f;
        #pragma unroll
        for (int k = 0; k < 8; ++k){
            float m = fmaf(a[k].x, a[k].x, a[k].y * a[k].y);
            p3 += (k & 4) ? -m : m;
            p7 += (k & 1) ? -m : m;
        }
        f0 = wsum32(p3);
        f1 = wsum32(p7);
    }

    // ================= MLP head =================
    float hv = 0.f;
    if (lane < 15){
        float4 w1v = __ldg(reinterpret_cast<const float4*>(W1) + lane);
        float z = __ldg(b1 + lane);
        z = fmaf(w1v.x, f0, z);
        z = fmaf(w1v.y, f1, z);
        z = fmaf(w1v.z, f2, z);
        z = fmaf(w1v.w, f3, z);
        hv = tanhf(z) * __ldg(W2 + lane);
    }
    float s = wsum32(hv);
    if (lane == 0){
        float zf = s + __ldg(b2);
        out[elem] = 1.0f / (1.0f + __expf(-zf));
    }
}

extern "C" void kernel_launch(void* const* d_in, const int* in_sizes, int n_in,
                              void* d_out, int out_size) {
    const float* x     = (const float*)d_in[0];
    const float* rz_p  = (const float*)d_in[1];
    const float* ry_p  = (const float*)d_in[2];
    const float* ry2_p = (const float*)d_in[3];
    const float* crx_p = (const float*)d_in[4];
    const float* u3_p  = (const float*)d_in[5];
    const float* u3b_p = (const float*)d_in[6];
    const float* W1    = (const float*)d_in[7];
    const float* b1    = (const float*)d_in[8];
    const float* W2    = (const float*)d_in[9];
    const float* b2    = (const float*)d_in[10];

    int B = in_sizes[0] / 32;          // x is (B, 32); one warp per element
    const int threads = 128;           // 4 warps/block
    int blocks = (B + 3) / 4;
    qcnn_kernel<<<blocks, threads>>>(x, rz_p, ry_p, ry2_p, crx_p, u3_p, u3b_p,
                                     W1, b1, W2, b2, (float*)d_out, B);
}

// round 12
// speedup vs baseline: 1.1391x; 1.1391x over previous
#include <cuda_runtime.h>
#include <cuda_bf16.h>

#define FULL 0xffffffffu

struct C2 { float x, y; };
__device__ __forceinline__ C2 mkc(float x, float y){ C2 c; c.x=x; c.y=y; return c; }
#define DUP(s) mkc((s),(s))

// ---------- packed f32x2 elementwise ops ----------
__device__ __forceinline__ C2 pfma(C2 a, C2 b, C2 c){
    C2 r;
    asm("{\n\t.reg .b64 A,B,C,D;\n\t"
        "mov.b64 A,{%2,%3};\n\t"
        "mov.b64 B,{%4,%5};\n\t"
        "mov.b64 C,{%6,%7};\n\t"
        "fma.rn.f32x2 D, A, B, C;\n\t"
        "mov.b64 {%0,%1}, D;\n\t}"
        : "=f"(r.x), "=f"(r.y)
        : "f"(a.x), "f"(a.y), "f"(b.x), "f"(b.y), "f"(c.x), "f"(c.y));
    return r;
}
__device__ __forceinline__ C2 pmul(C2 a, C2 b){
    C2 r;
    asm("{\n\t.reg .b64 A,B,D;\n\t"
        "mov.b64 A,{%2,%3};\n\t"
        "mov.b64 B,{%4,%5};\n\t"
        "mul.rn.f32x2 D, A, B;\n\t"
        "mov.b64 {%0,%1}, D;\n\t}"
        : "=f"(r.x), "=f"(r.y)
        : "f"(a.x), "f"(a.y), "f"(b.x), "f"(b.y));
    return r;
}
__device__ __forceinline__ C2 swapc(C2 v){ return mkc(v.y, v.x); }

// Mapping: 16 amplitudes/thread (k bits 0..3), 16 lanes/element, elem = lane bit 4.
//   odd qubits  (1,3,5,7) -> LOCAL k bits : q7->k1, q5->k2, q3->k4, q1->k8
//   even qubits (0,2,4,6) -> LANE bits    : q6->l1, q4->l2, q2->l4, q0->l8
template<int Q> struct QM {
    static constexpr bool local = (Q & 1) != 0;
    static constexpr int mask = local ? (1 << ((7 - Q) >> 1)) : (1 << ((6 - Q) >> 1));
};

__device__ __forceinline__ constexpr int cpop(int v){
    return (v&1)+((v>>1)&1)+((v>>2)&1)+((v>>3)&1);
}

__device__ __forceinline__ C2 cmul_s(C2 a, C2 b){
    return mkc(a.x*b.x - a.y*b.y, a.x*b.y + a.y*b.x);
}

// multiply a[k] by i^e(k), e(k) = (popc(k&MP) + 3*popc(k&MM)) & 3
template<int MP, int MM>
__device__ __forceinline__ void kdiag(C2 a[16]){
    #pragma unroll
    for (int k = 0; k < 16; ++k){
        const int e = (cpop(k & MP) + 3 * cpop(k & MM)) & 3;
        if (e == 1){ float t = a[k].x; a[k].x = -a[k].y; a[k].y =  t; }
        else if (e == 2){ a[k].x = -a[k].x; a[k].y = -a[k].y; }
        else if (e == 3){ float t = a[k].x; a[k].x =  a[k].y; a[k].y = -t; }
    }
}

// multiply ALL regs by complex W
__device__ __forceinline__ void diag_all(C2 a[16], C2 W){
    C2 P = DUP(W.x), Q = mkc(-W.y, W.y);
    #pragma unroll
    for (int k = 0; k < 16; ++k)
        a[k] = pfma(Q, swapc(a[k]), pmul(P, a[k]));
}

// multiply ALL regs by i where cb — SEL-based, ALU pipe
__device__ __forceinline__ void mul_i_sel(C2 a[16], bool cb){
    #pragma unroll
    for (int k = 0; k < 16; ++k){
        float nx = cb ? -a[k].y : a[k].x;
        float ny = cb ?  a[k].x : a[k].y;
        a[k].x = nx; a[k].y = ny;
    }
}

// multiply a[k] by w1^popc(k&MASK)
template<int MASK>
__device__ __forceinline__ void zpow(C2 a[16], C2 w1, C2 w2, C2 w3){
    #pragma unroll
    for (int k = 0; k < 16; ++k){
        const int p = cpop(k & MASK);
        if (p){
            C2 w = (p == 1) ? w1 : (p == 2) ? w2 : w3;
            a[k] = pfma(mkc(-w.y, w.y), swapc(a[k]), pmul(DUP(w.x), a[k]));
        }
    }
}

// FUSED RY(t1)->CX->RY(t2) on LOCAL target bit M; ctrl = runtime lane-uniform cb.
// cb=0: RY(t1+t2): out0 = cs*a0 - ss*a1 ; out1 = ss*a0 + cs*a1
// cb=1: X.RY(t1-t2): out0 = sd*a0 + cd*a1 ; out1 = cd*a0 - sd*a1
template<int M>
__device__ __forceinline__ void ry_loc_fused(C2 a[16], bool cb,
        float cs_, float ss_, float cd_, float sd_){
    C2 A0 = DUP(cb ? sd_ : cs_), B0 = DUP(cb ? cd_ : -ss_);
    C2 A1 = DUP(cb ? cd_ : ss_), B1 = DUP(cb ? -sd_ : cs_);
    #pragma unroll
    for (int k0 = 0; k0 < 16; ++k0) if (!(k0 & M)){
        int k1 = k0 | M;
        C2 a0 = a[k0], a1 = a[k1];
        a[k0] = pfma(A0, a0, pmul(B0, a1));
        a[k1] = pfma(A1, a0, pmul(B1, a1));
    }
}

// FUSED RY(t1)->CX->RY(t2) on LANE target bit LM; ctrl = LOCAL k-bit KM (compile-time).
// k&KM==0: RY(t1+t2): out = cs*a + (hi? ss:-ss)*p
// k&KM!=0: X.RY(t1-t2): out = (hi? -sd: sd)*a + cd*p
template<int LM, int KM>
__device__ __forceinline__ void ry_lane_fxk(C2 a[16],
        float cs_, float ss_, float cd_, float sd_, int hl){
    bool hi = (hl & LM) != 0;
    C2 CA0 = DUP(cs_),              CO0 = DUP(hi ? ss_ : -ss_);
    C2 CA1 = DUP(hi ? -sd_ : sd_),  CO1 = DUP(cd_);
    #pragma unroll
    for (int k = 0; k < 16; ++k){
        float px = __shfl_xor_sync(FULL, a[k].x, LM);
        float py = __shfl_xor_sync(FULL, a[k].y, LM);
        C2 p = mkc(px, py);
        if (k & KM) a[k] = pfma(CA1, a[k], pmul(CO1, p));
        else        a[k] = pfma(CA0, a[k], pmul(CO0, p));
    }
}

// X on local bit M, conditioned on runtime flag cb
template<int M>
__device__ __forceinline__ void xsel_local(C2 a[16], bool cb){
    #pragma unroll
    for (int k0 = 0; k0 < 16; ++k0) if (!(k0 & M)){
        int k1 = k0 | M;
        C2 t0 = a[k0], t1 = a[k1];
        a[k0] = cb ? t1 : t0;
        a[k1] = cb ? t0 : t1;
    }
}

// merged parity-0 CX stage: a[k] -> shfl_xor(a[k], k)
__device__ __forceinline__ void cx_shfl_id(C2 a[16]){
    #pragma unroll
    for (int k = 1; k < 16; ++k){
        a[k].x = __shfl_xor_sync(FULL, a[k].x, k);
        a[k].y = __shfl_xor_sync(FULL, a[k].y, k);
    }
}

// local RY on bit MT with per-k coeff selected by k&KM, then compile-time X if k&KM
template<int KM, int MT>
__device__ __forceinline__ void ry_local_sel_x(C2 a[16],
        float cs, float ss, float cd, float sd){
    #pragma unroll
    for (int k0 = 0; k0 < 16; ++k0) if (!(k0 & MT)){
        int k1 = k0 | MT;
        const float ce = (k0 & KM) ? cd : cs;
        const float se = (k0 & KM) ? sd : ss;
        C2 a0 = a[k0], a1 = a[k1];
        C2 n0 = pfma(DUP(ce), a0, pmul(DUP(-se), a1));
        C2 n1 = pfma(DUP(se), a0, pmul(DUP(ce), a1));
        if (k0 & KM){ a[k0] = n1; a[k1] = n0; }
        else        { a[k0] = n0; a[k1] = n1; }
    }
}

// compile-time local CX: control bit MC, target bit MT
template<int MC, int MT>
__device__ __forceinline__ void cx_local(C2 a[16]){
    #pragma unroll
    for (int k0 = 0; k0 < 16; ++k0) if ((k0 & MC) && !(k0 & MT)){
        int k1 = k0 | MT; C2 t = a[k0]; a[k0] = a[k1]; a[k1] = t;
    }
}

// ---------------- generic complex 1q gate ----------------
template<int Q>
__device__ __forceinline__ void g1(C2 a[16], C2 u00, C2 u01, C2 u10, C2 u11, int lane){
    constexpr int m = QM<Q>::mask;
    if constexpr (QM<Q>::local) {
        C2 x00 = DUP(u00.x), y00 = mkc(-u00.y, u00.y);
        C2 x01 = DUP(u01.x), y01 = mkc(-u01.y, u01.y);
        C2 x10 = DUP(u10.x), y10 = mkc(-u10.y, u10.y);
        C2 x11 = DUP(u11.x), y11 = mkc(-u11.y, u11.y);
        #pragma unroll
        for (int k0 = 0; k0 < 16; ++k0) if (!(k0 & m)) {
            int k1 = k0 | m;
            C2 a0 = a[k0], a1 = a[k1];
            C2 a0s = swapc(a0), a1s = swapc(a1);
            C2 t0 = pmul(x00, a0); t0 = pfma(y00, a0s, t0);
            t0 = pfma(x01, a1, t0); t0 = pfma(y01, a1s, t0);
            C2 t1 = pmul(x10, a0); t1 = pfma(y10, a0s, t1);
            t1 = pfma(x11, a1, t1); t1 = pfma(y11, a1s, t1);
            a[k0] = t0; a[k1] = t1;
        }
    } else {
        bool hi = (lane & m) != 0;
        C2 xA = hi ? DUP(u11.x) : DUP(u00.x);
        C2 yA = hi ? mkc(-u11.y, u11.y) : mkc(-u00.y, u00.y);
        C2 xB = hi ? DUP(u10.x) : DUP(u01.x);
        C2 yB = hi ? mkc(-u10.y, u10.y) : mkc(-u01.y, u01.y);
        #pragma unroll
        for (int k = 0; k < 16; ++k) {
            float px = __shfl_xor_sync(FULL, a[k].x, m);
            float py = __shfl_xor_sync(FULL, a[k].y, m);
            C2 t = pmul(xA, a[k]); t = pfma(yA, swapc(a[k]), t);
            t = pfma(xB, mkc(px, py), t); t = pfma(yB, mkc(py, px), t);
            a[k] = t;
        }
    }
}

// ---------------- CRX (packed) ----------------
template<int QC, int QT>
__device__ __forceinline__ void gcrx(C2 a[16], float c, float s, int lane){
    constexpr int mc = QM<QC>::mask, mt = QM<QT>::mask;
    if constexpr (QM<QC>::local && QM<QT>::local) {
        C2 c2 = DUP(c), sn = mkc(s, -s);
        #pragma unroll
        for (int k0 = 0; k0 < 16; ++k0) if ((k0 & mc) && !(k0 & mt)) {
            int k1 = k0 | mt;
            C2 a0 = a[k0], a1 = a[k1];
            a[k0] = pfma(c2, a0, pmul(sn, swapc(a1)));
            a[k1] = pfma(c2, a1, pmul(sn, swapc(a0)));
        }
    } else if constexpr (QM<QC>::local) {
        C2 c2 = DUP(c), sn = mkc(s, -s);
        #pragma unroll
        for (int k = 0; k < 16; ++k) if (k & mc) {
            float px = __shfl_xor_sync(FULL, a[k].x, mt);
            float py = __shfl_xor_sync(FULL, a[k].y, mt);
            a[k] = pfma(c2, a[k], pmul(sn, mkc(py, px)));
        }
    } else if constexpr (QM<QT>::local) {
        bool cb = (lane & mc) != 0;
        C2 c2 = DUP(cb ? c : 1.0f);
        C2 sn = cb ? mkc(s, -s) : mkc(0.f, 0.f);
        #pragma unroll
        for (int k0 = 0; k0 < 16; ++k0) if (!(k0 & mt)) {
            int k1 = k0 | mt;
            C2 a0 = a[k0], a1 = a[k1];
            a[k0] = pfma(c2, a0, pmul(sn, swapc(a1)));
            a[k1] = pfma(c2, a1, pmul(sn, swapc(a0)));
        }
    } else {
        bool cb = (lane & mc) != 0;
        C2 c2 = DUP(cb ? c : 1.0f);
        C2 sn = cb ? mkc(s, -s) : mkc(0.f, 0.f);
        #pragma unroll
        for (int k = 0; k < 16; ++k) {
            float px = __shfl_xor_sync(FULL, a[k].x, mt);
            float py = __shfl_xor_sync(FULL, a[k].y, mt);
            a[k] = pfma(c2, a[k], pmul(sn, mkc(py, px)));
        }
    }
}

// ---------------- real-state encode gates ----------------
template<int Q>
__device__ __forceinline__ void gryR(float r[16], float c, float s, int lane){
    constexpr int m = QM<Q>::mask;
    C2 c2 = DUP(c);
    if constexpr (QM<Q>::local) {
        if constexpr (m == 1) {
            C2 snn = mkc(-s, s);
            #pragma unroll
            for (int j = 0; j < 8; ++j) {
                C2 v = mkc(r[2*j], r[2*j+1]);
                C2 res = pfma(snn, swapc(v), pmul(c2, v));
                r[2*j] = res.x; r[2*j+1] = res.y;
            }
        } else {
            constexpr int pm = m >> 1;
            C2 s2 = DUP(s), ns2 = DUP(-s);
            #pragma unroll
            for (int j0 = 0; j0 < 8; ++j0) if (!(j0 & pm)) {
                int j1 = j0 | pm;
                C2 v0 = mkc(r[2*j0], r[2*j0+1]);
                C2 v1 = mkc(r[2*j1], r[2*j1+1]);
                C2 n0 = pfma(c2, v0, pmul(ns2, v1));
                C2 n1 = pfma(s2, v0, pmul(c2, v1));
                r[2*j0] = n0.x; r[2*j0+1] = n0.y;
                r[2*j1] = n1.x; r[2*j1+1] = n1.y;
            }
        }
    } else {
        C2 sg2 = (lane & m) ? DUP(s) : DUP(-s);
        #pragma unroll
        for (int j = 0; j < 8; ++j) {
            float px = __shfl_xor_sync(FULL, r[2*j],   m);
            float py = __shfl_xor_sync(FULL, r[2*j+1], m);
            C2 v = mkc(r[2*j], r[2*j+1]);
            C2 res = pfma(c2, v, pmul(sg2, mkc(px, py)));
            r[2*j] = res.x; r[2*j+1] = res.y;
        }
    }
}

template<int QC, int QT>
__device__ __forceinline__ void gcxR(float r[16], int lane){
    constexpr int mc = QM<QC>::mask, mt = QM<QT>::mask;
    if constexpr (QM<QC>::local && QM<QT>::local) {
        #pragma unroll
        for (int k0 = 0; k0 < 16; ++k0) if ((k0 & mc) && !(k0 & mt)) {
            int k1 = k0 | mt; float t = r[k0]; r[k0] = r[k1]; r[k1] = t;
        }
    } else if constexpr (QM<QC>::local) {
        #pragma unroll
        for (int k = 0; k < 16; ++k) if (k & mc)
            r[k] = __shfl_xor_sync(FULL, r[k], mt);
    } else if constexpr (QM<QT>::local) {
        bool cb = (lane & mc) != 0;
        #pragma unroll
        for (int k0 = 0; k0 < 16; ++k0) if (!(k0 & mt)) {
            int k1 = k0 | mt;
            float t0 = r[k0], t1 = r[k1];
            r[k0] = cb ? t1 : t0;
            r[k1] = cb ? t0 : t1;
        }
    } else {
        bool cb = (lane & mc) != 0;
        #pragma unroll
        for (int k = 0; k < 16; ++k) {
            float pv = __shfl_xor_sync(FULL, r[k], mt);
            r[k] = cb ? pv : r[k];
        }
    }
}

__device__ __forceinline__ float wsum16(float v){
    #pragma unroll
    for (int o = 8; o; o >>= 1) v += __shfl_xor_sync(FULL, v, o);
    return v;
}

__device__ __forceinline__ void u3m(const float* p, C2& U00, C2& U01, C2& U10, C2& U11){
    float t = p[0], ph = p[1], la = p[2];
    float st, ct, sp, cp, sl, cl, spl, cpl;
    __sincosf(t * 0.5f, &st, &ct);
    __sincosf(ph, &sp, &cp);
    __sincosf(la, &sl, &cl);
    __sincosf(ph + la, &spl, &cpl);
    U00 = mkc(ct, 0.f);
    U01 = mkc(-cl*st, -sl*st);
    U10 = mkc( cp*st,  sp*st);
    U11 = mkc(cpl*ct, spl*ct);
}

__global__ void __launch_bounds__(128, 8)
qcnn_kernel(const float* __restrict__ x,
            const float* __restrict__ rz_p,  const float* __restrict__ ry_p,
            const float* __restrict__ ry2_p, const float* __restrict__ crx_p,
            const float* __restrict__ u3_p,  const float* __restrict__ u3b_p,
            const float* __restrict__ W1,    const float* __restrict__ b1,
            const float* __restrict__ W2,    const float* __restrict__ b2,
            float* __restrict__ out, int B)
{
    const int warp = (blockIdx.x * blockDim.x + threadIdx.x) >> 5;
    const int lane = threadIdx.x & 31;
    const int hl   = lane & 15;
    const int elem = warp * 2 + (lane >> 4);
    if (warp * 2 >= B) return;
    const int e = (elem < B) ? elem : (B - 1);

    // ================= encode (state purely REAL) =================
    float2 av = reinterpret_cast<const float2*>(x)[e * 16 + hl];
    float c0, s0, c1, s1;
    __sincosf(0.5f * av.x, &s0, &c0);
    __sincosf(0.5f * av.y, &s1, &c1);

    float r[16];
    #pragma unroll
    for (int k = 0; k < 16; ++k) r[k] = 0.0f;
    r[0] = (hl == 0) ? 1.0f : 0.0f;

    #define RYQ(CY,Q) do { \
        const int idx_ = (CY)*8 + (Q); \
        int src_ = (lane & 16) | (idx_ >> 1); \
        float cc_ = __shfl_sync(FULL, ((idx_ & 1) ? c1 : c0), src_); \
        float ss_ = __shfl_sync(FULL, ((idx_ & 1) ? s1 : s0), src_); \
        gryR<Q>(r, cc_, ss_, lane); } while(0)

    #define ENC_CYC(CY) \
        RYQ(CY,0); RYQ(CY,1); RYQ(CY,2); RYQ(CY,3); \
        RYQ(CY,4); RYQ(CY,5); RYQ(CY,6); RYQ(CY,7); \
        gcxR<0,1>(r,lane); gcxR<1,2>(r,lane); gcxR<2,3>(r,lane); gcxR<3,4>(r,lane); \
        gcxR<4,5>(r,lane); gcxR<5,6>(r,lane); gcxR<6,7>(r,lane); gcxR<7,0>(r,lane);

    ENC_CYC(0) ENC_CYC(1) ENC_CYC(2) ENC_CYC(3)

    // ================= psi1 FIRST (short; r stays live only here) ====
    C2 a[16];
    #pragma unroll
    for (int k = 0; k < 16; ++k) a[k] = mkc(r[k], 0.f);

    {   // layer 0
        float xc, xs;
        __sincosf(crx_p[0] * 0.5f, &xs, &xc);
        gcrx<0,1>(a, xc, xs, lane);
        gcrx<2,3>(a, xc, xs, lane);
        gcrx<4,5>(a, xc, xs, lane);
        gcrx<6,7>(a, xc, xs, lane);
        gcrx<1,2>(a, xc, xs, lane);
        gcrx<3,4>(a, xc, xs, lane);
        gcrx<5,6>(a, xc, xs, lane);
        C2 U00, U01, U10, U11;
        u3m(u3b_p, U00, U01, U10, U11);
        g1<1>(a, U00, U01, U10, U11, lane);
        g1<3>(a, U00, U01, U10, U11, lane);
        g1<5>(a, U00, U01, U10, U11, lane);
        g1<7>(a, U00, U01, U10, U11, lane);
    }
    {   // layer 1
        float xc, xs;
        __sincosf(crx_p[1] * 0.5f, &xs, &xc);
        gcrx<1,3>(a, xc, xs, lane);
        gcrx<5,7>(a, xc, xs, lane);
        gcrx<3,5>(a, xc, xs, lane);
        C2 U00, U01, U10, U11;
        u3m(u3b_p + 3, U00, U01, U10, U11);
        g1<3>(a, U00, U01, U10, U11, lane);
        g1<7>(a, U00, U01, U10, U11, lane);
    }

    float f2, f3;
    {
        float p3 = 0.f, p7 = 0.f;
        #pragma unroll
        for (int k = 0; k < 16; ++k) {
            float m = fmaf(a[k].x, a[k].x, a[k].y * a[k].y);
            p3 += (k & 4) ? -m : m;
            p7 += (k & 1) ? -m : m;
        }
        f2 = wsum16(p3);
        f3 = wsum16(p7);
    }

    // ================= psi0 (merged + fused stages) =================
    #pragma unroll
    for (int k = 0; k < 16; ++k) a[k] = mkc(r[k], 0.f);

    {   // ---- layer 0 ----
        float zs, zc;
        __sincosf(rz_p[0], &zs, &zc);
        C2 w1 = mkc(zc, zs);
        C2 w2 = cmul_s(w1, w1);
        C2 w3 = cmul_s(w2, w1);
        C2 w4 = cmul_s(w2, w2);
        float yc, ys, y2c, y2s;
        __sincosf(ry_p[0]  * 0.5f, &ys,  &yc);
        __sincosf(ry2_p[0] * 0.5f, &y2s, &y2c);
        const float cs_ = yc*y2c - ys*y2s, ss_ = ys*y2c + yc*y2s;   // t1+t2
        const float cd_ = yc*y2c + ys*y2s, sd_ = ys*y2c - yc*y2s;   // t1-t2

        // ---- parity-0 sweep ----
        kdiag<0, 15>(a);
        cx_shfl_id(a);
        {   // merged diag: W = w1^popc(hl)
            int p = __popc((unsigned)hl);
            C2 W  = (p & 1) ? w1 : mkc(1.f, 0.f);
            C2 Wb = (p & 2) ? w2 : mkc(1.f, 0.f);
            W = cmul_s(W, Wb);
            W.x = (p & 4) ? w4.x : W.x;
            W.y = (p & 4) ? w4.y : W.y;
            diag_all(a, W);
        }
        // fused RY-CX-RY per pair (coefficient-select, no runtime SELs)
        ry_loc_fused<8>(a, (hl & 8) != 0, cs_, ss_, cd_, sd_);
        ry_loc_fused<4>(a, (hl & 4) != 0, cs_, ss_, cd_, sd_);
        ry_loc_fused<2>(a, (hl & 2) != 0, cs_, ss_, cd_, sd_);
        ry_loc_fused<1>(a, (hl & 1) != 0, cs_, ss_, cd_, sd_);
        cx_shfl_id(a);
        mul_i_sel(a, (hl & 8) != 0);   // merged gate-8 x4 + parity-1 gate-1 x3

        // ---- parity-1 sweep ----
        xsel_local<8>(a, (hl & 4) != 0);   // gate-2 CX's
        xsel_local<4>(a, (hl & 2) != 0);
        xsel_local<2>(a, (hl & 1) != 0);
        zpow<14>(a, w1, w2, w3);           // gate-3 merged RZ
        // fused RY-CX-RY on lane targets (X folded into per-k coeff select)
        ry_lane_fxk<4, 8>(a, cs_, ss_, cd_, sd_, hl);
        ry_lane_fxk<2, 4>(a, cs_, ss_, cd_, sd_, hl);
        ry_lane_fxk<1, 2>(a, cs_, ss_, cd_, sd_, hl);
        xsel_local<8>(a, (hl & 4) != 0);   // gate-7 CX's
        xsel_local<4>(a, (hl & 2) != 0);
        xsel_local<2>(a, (hl & 1) != 0);
        kdiag<14, 0>(a);                   // gate-8

        C2 U00, U01, U10, U11;
        u3m(u3_p, U00, U01, U10, U11);
        g1<1>(a, U00, U01, U10, U11, lane);
        g1<3>(a, U00, U01, U10, U11, lane);
        g1<5>(a, U00, U01, U10, U11, lane);
        g1<7>(a, U00, U01, U10, U11, lane);
    }

    {   // ---- layer 1 (all local) ----
        float zs, zc;
        __sincosf(rz_p[1], &zs, &zc);
        C2 w1 = mkc(zc, zs);
        C2 w2 = cmul_s(w1, w1);
        float yc, ys, y2c, y2s;
        __sincosf(ry_p[1]  * 0.5f, &ys,  &yc);
        __sincosf(ry2_p[1] * 0.5f, &y2s, &y2c);
        const float cs_ = yc*y2c - ys*y2s, ss_ = ys*y2c + yc*y2s;
        const float cd_ = yc*y2c + ys*y2s, sd_ = ys*y2c - yc*y2s;

        kdiag<0, 5>(a);
        cx_local<4, 8>(a);
        cx_local<1, 2>(a);
        zpow<10>(a, w1, w2, w2);
        ry_local_sel_x<8, 4>(a, cs_, ss_, cd_, sd_);
        ry_local_sel_x<2, 1>(a, cs_, ss_, cd_, sd_);
        cx_local<4, 8>(a);
        cx_local<1, 2>(a);
        kdiag<10, 2>(a);

        cx_local<2, 4>(a);
        zpow<4>(a, w1, w2, w2);
        ry_local_sel_x<4, 2>(a, cs_, ss_, cd_, sd_);
        cx_local<2, 4>(a);
        kdiag<4, 0>(a);

        C2 U00, U01, U10, U11;
        u3m(u3_p + 3, U00, U01, U10, U11);
        g1<3>(a, U00, U01, U10, U11, lane);
        g1<7>(a, U00, U01, U10, U11, lane);
    }

    float f0, f1;
    {
        float p3 = 0.f, p7 = 0.f;
        #pragma unroll
        for (int k = 0; k < 16; ++k) {
            float m = fmaf(a[k].x, a[k].x, a[k].y * a[k].y);
            p3 += (k & 4) ? -m : m;
            p7 += (k & 1) ? -m : m;
        }
        f0 = wsum16(p3);
        f1 = wsum16(p7);
    }

    // ================= MLP head =================
    float hv = 0.f;
    if (hl < 15) {
        float z = b1[hl];
        z = fmaf(W1[hl*4+0], f0, z);
        z = fmaf(W1[hl*4+1], f1, z);
        z = fmaf(W1[hl*4+2], f2, z);
        z = fmaf(W1[hl*4+3], f3, z);
        hv = tanhf(z) * W2[hl];
    }
    float s = wsum16(hv);
    if (hl == 0 && elem < B) {
        float zf = s + b2[0];
        out[elem] = 1.0f / (1.0f + __expf(-zf));
    }
}

extern "C" void kernel_launch(void* const* d_in, const int* in_sizes, int n_in,
                              void* d_out, int out_size) {
    const float* x     = (const float*)d_in[0];
    const float* rz_p  = (const float*)d_in[1];
    const float* ry_p  = (const float*)d_in[2];
    const float* ry2_p = (const float*)d_in[3];
    const float* crx_p = (const float*)d_in[4];
    const float* u3_p  = (const float*)d_in[5];
    const float* u3b_p = (const float*)d_in[6];
    const float* W1    = (const float*)d_in[7];
    const float* b1    = (const float*)d_in[8];
    const float* W2    = (const float*)d_in[9];
    const float* b2    = (const float*)d_in[10];

    int B = in_sizes[0] / 32;          // x is (B, 32)
    const int threads = 128;           // 4 warps/block, 8 elements/block
    int blocks = (B + 7) / 8;
    qcnn_kernel<<<blocks, threads>>>(x, rz_p, ry_p, ry2_p, crx_p, u3_p, u3b_p,
                                     W1, b1, W2, b2, (float*)d_out, B);
}

// round 13
// speedup vs baseline: 1.1404x; 1.0011x over previous
#include <cuda_runtime.h>
#include <cuda_bf16.h>

#define FULL 0xffffffffu

struct C2 { float x, y; };
__device__ __forceinline__ C2 mkc(float x, float y){ C2 c; c.x=x; c.y=y; return c; }
#define DUP(s) mkc((s),(s))

// ---------- packed f32x2 elementwise ops ----------
__device__ __forceinline__ C2 pfma(C2 a, C2 b, C2 c){
    C2 r;
    asm("{\n\t.reg .b64 A,B,C,D;\n\t"
        "mov.b64 A,{%2,%3};\n\t"
        "mov.b64 B,{%4,%5};\n\t"
        "mov.b64 C,{%6,%7};\n\t"
        "fma.rn.f32x2 D, A, B, C;\n\t"
        "mov.b64 {%0,%1}, D;\n\t}"
        : "=f"(r.x), "=f"(r.y)
        : "f"(a.x), "f"(a.y), "f"(b.x), "f"(b.y), "f"(c.x), "f"(c.y));
    return r;
}
__device__ __forceinline__ C2 pmul(C2 a, C2 b){
    C2 r;
    asm("{\n\t.reg .b64 A,B,D;\n\t"
        "mov.b64 A,{%2,%3};\n\t"
        "mov.b64 B,{%4,%5};\n\t"
        "mul.rn.f32x2 D, A, B;\n\t"
        "mov.b64 {%0,%1}, D;\n\t}"
        : "=f"(r.x), "=f"(r.y)
        : "f"(a.x), "f"(a.y), "f"(b.x), "f"(b.y));
    return r;
}
__device__ __forceinline__ C2 swapc(C2 v){ return mkc(v.y, v.x); }

// Mapping: 16 amplitudes/thread (k bits 0..3), 16 lanes/element, elem = lane bit 4.
//   odd qubits  (1,3,5,7) -> LOCAL k bits : q7->k1, q5->k2, q3->k4, q1->k8
//   even qubits (0,2,4,6) -> LANE bits    : q6->l1, q4->l2, q2->l4, q0->l8
template<int Q> struct QM {
    static constexpr bool local = (Q & 1) != 0;
    static constexpr int mask = local ? (1 << ((7 - Q) >> 1)) : (1 << ((6 - Q) >> 1));
};

__device__ __forceinline__ constexpr int cpop(int v){
    return (v&1)+((v>>1)&1)+((v>>2)&1)+((v>>3)&1);
}

__device__ __forceinline__ C2 cmul_s(C2 a, C2 b){
    return mkc(a.x*b.x - a.y*b.y, a.x*b.y + a.y*b.x);
}

// multiply a[k] by i^e(k), e(k) = (popc(k&MP) + 3*popc(k&MM)) & 3
template<int MP, int MM>
__device__ __forceinline__ void kdiag(C2 a[16]){
    #pragma unroll
    for (int k = 0; k < 16; ++k){
        const int e = (cpop(k & MP) + 3 * cpop(k & MM)) & 3;
        if (e == 1){ float t = a[k].x; a[k].x = -a[k].y; a[k].y =  t; }
        else if (e == 2){ a[k].x = -a[k].x; a[k].y = -a[k].y; }
        else if (e == 3){ float t = a[k].x; a[k].x =  a[k].y; a[k].y = -t; }
    }
}

// multiply ALL regs by complex W
__device__ __forceinline__ void diag_all(C2 a[16], C2 W){
    C2 P = DUP(W.x), Q = mkc(-W.y, W.y);
    #pragma unroll
    for (int k = 0; k < 16; ++k)
        a[k] = pfma(Q, swapc(a[k]), pmul(P, a[k]));
}

// multiply ALL regs by i where cb — SEL-based, ALU pipe
__device__ __forceinline__ void mul_i_sel(C2 a[16], bool cb){
    #pragma unroll
    for (int k = 0; k < 16; ++k){
        float nx = cb ? -a[k].y : a[k].x;
        float ny = cb ?  a[k].x : a[k].y;
        a[k].x = nx; a[k].y = ny;
    }
}

// multiply a[k] by w1^popc(k&MASK)
template<int MASK>
__device__ __forceinline__ void zpow(C2 a[16], C2 w1, C2 w2, C2 w3){
    #pragma unroll
    for (int k = 0; k < 16; ++k){
        const int p = cpop(k & MASK);
        if (p){
            C2 w = (p == 1) ? w1 : (p == 2) ? w2 : w3;
            a[k] = pfma(mkc(-w.y, w.y), swapc(a[k]), pmul(DUP(w.x), a[k]));
        }
    }
}

// FUSED RY(t1)->CX->RY(t2) on LOCAL target bit M; ctrl = runtime lane-uniform cb.
template<int M>
__device__ __forceinline__ void ry_loc_fused(C2 a[16], bool cb,
        float cs_, float ss_, float cd_, float sd_){
    C2 A0 = DUP(cb ? sd_ : cs_), B0 = DUP(cb ? cd_ : -ss_);
    C2 A1 = DUP(cb ? cd_ : ss_), B1 = DUP(cb ? -sd_ : cs_);
    #pragma unroll
    for (int k0 = 0; k0 < 16; ++k0) if (!(k0 & M)){
        int k1 = k0 | M;
        C2 a0 = a[k0], a1 = a[k1];
        a[k0] = pfma(A0, a0, pmul(B0, a1));
        a[k1] = pfma(A1, a0, pmul(B1, a1));
    }
}

// FUSED RY(t1)->CX->RY(t2) on LANE target bit LM; ctrl = LOCAL k-bit KM.
// (shuffle value feeds the LAST fma — pmul on resident value issues first)
template<int LM, int KM>
__device__ __forceinline__ void ry_lane_fxk(C2 a[16],
        float cs_, float ss_, float cd_, float sd_, int hl){
    bool hi = (hl & LM) != 0;
    C2 CA0 = DUP(cs_),              CO0 = DUP(hi ? ss_ : -ss_);
    C2 CA1 = DUP(hi ? -sd_ : sd_),  CO1 = DUP(cd_);
    #pragma unroll
    for (int k = 0; k < 16; ++k){
        float px = __shfl_xor_sync(FULL, a[k].x, LM);
        float py = __shfl_xor_sync(FULL, a[k].y, LM);
        C2 p = mkc(px, py);
        if (k & KM) a[k] = pfma(CO1, p, pmul(CA1, a[k]));
        else        a[k] = pfma(CO0, p, pmul(CA0, a[k]));
    }
}

// X on local bit M, conditioned on runtime flag cb
template<int M>
__device__ __forceinline__ void xsel_local(C2 a[16], bool cb){
    #pragma unroll
    for (int k0 = 0; k0 < 16; ++k0) if (!(k0 & M)){
        int k1 = k0 | M;
        C2 t0 = a[k0], t1 = a[k1];
        a[k0] = cb ? t1 : t0;
        a[k1] = cb ? t0 : t1;
    }
}

// merged parity-0 CX stage: a[k] -> shfl_xor(a[k], k)
__device__ __forceinline__ void cx_shfl_id(C2 a[16]){
    #pragma unroll
    for (int k = 1; k < 16; ++k){
        a[k].x = __shfl_xor_sync(FULL, a[k].x, k);
        a[k].y = __shfl_xor_sync(FULL, a[k].y, k);
    }
}

// local RY on bit MT with per-k coeff selected by k&KM, then compile-time X if k&KM
template<int KM, int MT>
__device__ __forceinline__ void ry_local_sel_x(C2 a[16],
        float cs, float ss, float cd, float sd){
    #pragma unroll
    for (int k0 = 0; k0 < 16; ++k0) if (!(k0 & MT)){
        int k1 = k0 | MT;
        const float ce = (k0 & KM) ? cd : cs;
        const float se = (k0 & KM) ? sd : ss;
        C2 a0 = a[k0], a1 = a[k1];
        C2 n0 = pfma(DUP(ce), a0, pmul(DUP(-se), a1));
        C2 n1 = pfma(DUP(se), a0, pmul(DUP(ce), a1));
        if (k0 & KM){ a[k0] = n1; a[k1] = n0; }
        else        { a[k0] = n0; a[k1] = n1; }
    }
}

// compile-time local CX: control bit MC, target bit MT
template<int MC, int MT>
__device__ __forceinline__ void cx_local(C2 a[16]){
    #pragma unroll
    for (int k0 = 0; k0 < 16; ++k0) if ((k0 & MC) && !(k0 & MT)){
        int k1 = k0 | MT; C2 t = a[k0]; a[k0] = a[k1]; a[k1] = t;
    }
}

// ---------------- generic complex 1q gate ----------------
template<int Q>
__device__ __forceinline__ void g1(C2 a[16], C2 u00, C2 u01, C2 u10, C2 u11, int lane){
    constexpr int m = QM<Q>::mask;
    if constexpr (QM<Q>::local) {
        C2 x00 = DUP(u00.x), y00 = mkc(-u00.y, u00.y);
        C2 x01 = DUP(u01.x), y01 = mkc(-u01.y, u01.y);
        C2 x10 = DUP(u10.x), y10 = mkc(-u10.y, u10.y);
        C2 x11 = DUP(u11.x), y11 = mkc(-u11.y, u11.y);
        #pragma unroll
        for (int k0 = 0; k0 < 16; ++k0) if (!(k0 & m)) {
            int k1 = k0 | m;
            C2 a0 = a[k0], a1 = a[k1];
            C2 a0s = swapc(a0), a1s = swapc(a1);
            C2 t0 = pmul(x00, a0); t0 = pfma(y00, a0s, t0);
            t0 = pfma(x01, a1, t0); t0 = pfma(y01, a1s, t0);
            C2 t1 = pmul(x10, a0); t1 = pfma(y10, a0s, t1);
            t1 = pfma(x11, a1, t1); t1 = pfma(y11, a1s, t1);
            a[k0] = t0; a[k1] = t1;
        }
    } else {
        bool hi = (lane & m) != 0;
        C2 xA = hi ? DUP(u11.x) : DUP(u00.x);
        C2 yA = hi ? mkc(-u11.y, u11.y) : mkc(-u00.y, u00.y);
        C2 xB = hi ? DUP(u10.x) : DUP(u01.x);
        C2 yB = hi ? mkc(-u10.y, u10.y) : mkc(-u01.y, u01.y);
        #pragma unroll
        for (int k = 0; k < 16; ++k) {
            float px = __shfl_xor_sync(FULL, a[k].x, m);
            float py = __shfl_xor_sync(FULL, a[k].y, m);
            C2 t = pmul(xA, a[k]); t = pfma(yA, swapc(a[k]), t);
            t = pfma(xB, mkc(px, py), t); t = pfma(yB, mkc(py, px), t);
            a[k] = t;
        }
    }
}

// ---------------- CRX (packed; shuffle value last-in-chain) ----------------
template<int QC, int QT>
__device__ __forceinline__ void gcrx(C2 a[16], float c, float s, int lane){
    constexpr int mc = QM<QC>::mask, mt = QM<QT>::mask;
    if constexpr (QM<QC>::local && QM<QT>::local) {
        C2 c2 = DUP(c), sn = mkc(s, -s);
        #pragma unroll
        for (int k0 = 0; k0 < 16; ++k0) if ((k0 & mc) && !(k0 & mt)) {
            int k1 = k0 | mt;
            C2 a0 = a[k0], a1 = a[k1];
            a[k0] = pfma(c2, a0, pmul(sn, swapc(a1)));
            a[k1] = pfma(c2, a1, pmul(sn, swapc(a0)));
        }
    } else if constexpr (QM<QC>::local) {
        C2 c2 = DUP(c), sn = mkc(s, -s);
        #pragma unroll
        for (int k = 0; k < 16; ++k) if (k & mc) {
            float px = __shfl_xor_sync(FULL, a[k].x, mt);
            float py = __shfl_xor_sync(FULL, a[k].y, mt);
            a[k] = pfma(sn, mkc(py, px), pmul(c2, a[k]));
        }
    } else if constexpr (QM<QT>::local) {
        bool cb = (lane & mc) != 0;
        C2 c2 = DUP(cb ? c : 1.0f);
        C2 sn = cb ? mkc(s, -s) : mkc(0.f, 0.f);
        #pragma unroll
        for (int k0 = 0; k0 < 16; ++k0) if (!(k0 & mt)) {
            int k1 = k0 | mt;
            C2 a0 = a[k0], a1 = a[k1];
            a[k0] = pfma(c2, a0, pmul(sn, swapc(a1)));
            a[k1] = pfma(c2, a1, pmul(sn, swapc(a0)));
        }
    } else {
        bool cb = (lane & mc) != 0;
        C2 c2 = DUP(cb ? c : 1.0f);
        C2 sn = cb ? mkc(s, -s) : mkc(0.f, 0.f);
        #pragma unroll
        for (int k = 0; k < 16; ++k) {
            float px = __shfl_xor_sync(FULL, a[k].x, mt);
            float py = __shfl_xor_sync(FULL, a[k].y, mt);
            a[k] = pfma(sn, mkc(py, px), pmul(c2, a[k]));
        }
    }
}

// ---------------- real-state encode gates ----------------
template<int Q>
__device__ __forceinline__ void gryR(float r[16], float c, float s, int lane){
    constexpr int m = QM<Q>::mask;
    C2 c2 = DUP(c);
    if constexpr (QM<Q>::local) {
        if constexpr (m == 1) {
            C2 snn = mkc(-s, s);
            #pragma unroll
            for (int j = 0; j < 8; ++j) {
                C2 v = mkc(r[2*j], r[2*j+1]);
                C2 res = pfma(snn, swapc(v), pmul(c2, v));
                r[2*j] = res.x; r[2*j+1] = res.y;
            }
        } else {
            constexpr int pm = m >> 1;
            C2 s2 = DUP(s), ns2 = DUP(-s);
            #pragma unroll
            for (int j0 = 0; j0 < 8; ++j0) if (!(j0 & pm)) {
                int j1 = j0 | pm;
                C2 v0 = mkc(r[2*j0], r[2*j0+1]);
                C2 v1 = mkc(r[2*j1], r[2*j1+1]);
                C2 n0 = pfma(c2, v0, pmul(ns2, v1));
                C2 n1 = pfma(s2, v0, pmul(c2, v1));
                r[2*j0] = n0.x; r[2*j0+1] = n0.y;
                r[2*j1] = n1.x; r[2*j1+1] = n1.y;
            }
        }
    } else {
        C2 sg2 = (lane & m) ? DUP(s) : DUP(-s);
        #pragma unroll
        for (int j = 0; j < 8; ++j) {
            float px = __shfl_xor_sync(FULL, r[2*j],   m);
            float py = __shfl_xor_sync(FULL, r[2*j+1], m);
            C2 v = mkc(r[2*j], r[2*j+1]);
            C2 res = pfma(sg2, mkc(px, py), pmul(c2, v));   // shfl feeds last fma
            r[2*j] = res.x; r[2*j+1] = res.y;
        }
    }
}

template<int QC, int QT>
__device__ __forceinline__ void gcxR(float r[16], int lane){
    constexpr int mc = QM<QC>::mask, mt = QM<QT>::mask;
    if constexpr (QM<QC>::local && QM<QT>::local) {
        #pragma unroll
        for (int k0 = 0; k0 < 16; ++k0) if ((k0 & mc) && !(k0 & mt)) {
            int k1 = k0 | mt; float t = r[k0]; r[k0] = r[k1]; r[k1] = t;
        }
    } else if constexpr (QM<QC>::local) {
        #pragma unroll
        for (int k = 0; k < 16; ++k) if (k & mc)
            r[k] = __shfl_xor_sync(FULL, r[k], mt);
    } else if constexpr (QM<QT>::local) {
        bool cb = (lane & mc) != 0;
        #pragma unroll
        for (int k0 = 0; k0 < 16; ++k0) if (!(k0 & mt)) {
            int k1 = k0 | mt;
            float t0 = r[k0], t1 = r[k1];
            r[k0] = cb ? t1 : t0;
            r[k1] = cb ? t0 : t1;
        }
    } else {
        bool cb = (lane & mc) != 0;
        #pragma unroll
        for (int k = 0; k < 16; ++k) {
            float pv = __shfl_xor_sync(FULL, r[k], mt);
            r[k] = cb ? pv : r[k];
        }
    }
}

__device__ __forceinline__ float wsum16(float v){
    #pragma unroll
    for (int o = 8; o; o >>= 1) v += __shfl_xor_sync(FULL, v, o);
    return v;
}

__device__ __forceinline__ void u3m(const float* p, C2& U00, C2& U01, C2& U10, C2& U11){
    float t = p[0], ph = p[1], la = p[2];
    float st, ct, sp, cp, sl, cl, spl, cpl;
    __sincosf(t * 0.5f, &st, &ct);
    __sincosf(ph, &sp, &cp);
    __sincosf(la, &sl, &cl);
    __sincosf(ph + la, &spl, &cpl);
    U00 = mkc(ct, 0.f);
    U01 = mkc(-cl*st, -sl*st);
    U10 = mkc( cp*st,  sp*st);
    U11 = mkc(cpl*ct, spl*ct);
}

__global__ void __launch_bounds__(64, 16)
qcnn_kernel(const float* __restrict__ x,
            const float* __restrict__ rz_p,  const float* __restrict__ ry_p,
            const float* __restrict__ ry2_p, const float* __restrict__ crx_p,
            const float* __restrict__ u3_p,  const float* __restrict__ u3b_p,
            const float* __restrict__ W1,    const float* __restrict__ b1,
            const float* __restrict__ W2,    const float* __restrict__ b2,
            float* __restrict__ out, int B)
{
    const int warp = (blockIdx.x * blockDim.x + threadIdx.x) >> 5;
    const int lane = threadIdx.x & 31;
    const int hl   = lane & 15;
    const int elem = warp * 2 + (lane >> 4);
    if (warp * 2 >= B) return;
    const int e = (elem < B) ? elem : (B - 1);

    // ================= encode (state purely REAL) =================
    float2 av = reinterpret_cast<const float2*>(x)[e * 16 + hl];
    float c0, s0, c1, s1;
    __sincosf(0.5f * av.x, &s0, &c0);
    __sincosf(0.5f * av.y, &s1, &c1);

    #define GETC(IDX) __shfl_sync(FULL, (((IDX) & 1) ? c1 : c0), (lane & 16) | ((IDX) >> 1))
    #define GETS(IDX) __shfl_sync(FULL, (((IDX) & 1) ? s1 : s0), (lane & 16) | ((IDX) >> 1))

    float r[16];
    {   // ---- cycle 0: product state directly (RYs on |0..0> have no butterflies)
        float qc[8], qs[8];
        #pragma unroll
        for (int q = 0; q < 8; ++q){ qc[q] = GETC(q); qs[q] = GETS(q); }
        // lane factor over q0(l8), q2(l4), q4(l2), q6(l1)
        float F = ((hl & 8) ? qs[0] : qc[0]) * ((hl & 4) ? qs[2] : qc[2])
                * ((hl & 2) ? qs[4] : qc[4]) * ((hl & 1) ? qs[6] : qc[6]);
        // local: q1->k8, q3->k4, q5->k2, q7->k1
        float u_[4] = { qc[1]*qc[3], qc[1]*qs[3], qs[1]*qc[3], qs[1]*qs[3] };
        float v_[4] = { qc[5]*qc[7], qc[5]*qs[7], qs[5]*qc[7], qs[5]*qs[7] };
        #pragma unroll
        for (int i = 0; i < 4; ++i) u_[i] *= F;
        #pragma unroll
        for (int k = 0; k < 16; ++k) r[k] = u_[k >> 2] * v_[k & 3];
    }

    #define RYQ(CY,Q) do { \
        const int idx_ = (CY)*8 + (Q); \
        float cc_ = GETC(idx_); \
        float ss_ = GETS(idx_); \
        gryR<Q>(r, cc_, ss_, lane); } while(0)

    #define CX_RING() \
        gcxR<0,1>(r,lane); gcxR<1,2>(r,lane); gcxR<2,3>(r,lane); gcxR<3,4>(r,lane); \
        gcxR<4,5>(r,lane); gcxR<5,6>(r,lane); gcxR<6,7>(r,lane); gcxR<7,0>(r,lane);

    #define ENC_CYC(CY) \
        RYQ(CY,0); RYQ(CY,1); RYQ(CY,2); RYQ(CY,3); \
        RYQ(CY,4); RYQ(CY,5); RYQ(CY,6); RYQ(CY,7); \
        CX_RING()

    CX_RING()                 // cycle 0's ring
    ENC_CYC(1) ENC_CYC(2) ENC_CYC(3)

    // ================= psi1 FIRST (short; r stays live only here) ====
    C2 a[16];
    #pragma unroll
    for (int k = 0; k < 16; ++k) a[k] = mkc(r[k], 0.f);

    {   // layer 0
        float xc, xs;
        __sincosf(crx_p[0] * 0.5f, &xs, &xc);
        gcrx<0,1>(a, xc, xs, lane);
        gcrx<2,3>(a, xc, xs, lane);
        gcrx<4,5>(a, xc, xs, lane);
        gcrx<6,7>(a, xc, xs, lane);
        gcrx<1,2>(a, xc, xs, lane);
        gcrx<3,4>(a, xc, xs, lane);
        gcrx<5,6>(a, xc, xs, lane);
        C2 U00, U01, U10, U11;
        u3m(u3b_p, U00, U01, U10, U11);
        g1<1>(a, U00, U01, U10, U11, lane);
        g1<3>(a, U00, U01, U10, U11, lane);
        g1<5>(a, U00, U01, U10, U11, lane);
        g1<7>(a, U00, U01, U10, U11, lane);
    }
    {   // layer 1
        float xc, xs;
        __sincosf(crx_p[1] * 0.5f, &xs, &xc);
        gcrx<1,3>(a, xc, xs, lane);
        gcrx<5,7>(a, xc, xs, lane);
        gcrx<3,5>(a, xc, xs, lane);
        C2 U00, U01, U10, U11;
        u3m(u3b_p + 3, U00, U01, U10, U11);
        g1<3>(a, U00, U01, U10, U11, lane);
        g1<7>(a, U00, U01, U10, U11, lane);
    }

    float f2, f3;
    {
        float p3 = 0.f, p7 = 0.f;
        #pragma unroll
        for (int k = 0; k < 16; ++k) {
            float m = fmaf(a[k].x, a[k].x, a[k].y * a[k].y);
            p3 += (k & 4) ? -m : m;
            p7 += (k & 1) ? -m : m;
        }
        f2 = wsum16(p3);
        f3 = wsum16(p7);
    }

    // ================= psi0 (merged + fused stages) =================
    #pragma unroll
    for (int k = 0; k < 16; ++k) a[k] = mkc(r[k], 0.f);

    {   // ---- layer 0 ----
        float zs, zc;
        __sincosf(rz_p[0], &zs, &zc);
        C2 w1 = mkc(zc, zs);
        C2 w2 = cmul_s(w1, w1);
        C2 w3 = cmul_s(w2, w1);
        C2 w4 = cmul_s(w2, w2);
        float yc, ys, y2c, y2s;
        __sincosf(ry_p[0]  * 0.5f, &ys,  &yc);
        __sincosf(ry2_p[0] * 0.5f, &y2s, &y2c);
        const float cs_ = yc*y2c - ys*y2s, ss_ = ys*y2c + yc*y2s;   // t1+t2
        const float cd_ = yc*y2c + ys*y2s, sd_ = ys*y2c - yc*y2s;   // t1-t2

        // ---- parity-0 sweep ----
        kdiag<0, 15>(a);
        cx_shfl_id(a);
        {   // merged diag: W = w1^popc(hl)
            int p = __popc((unsigned)hl);
            C2 W  = (p & 1) ? w1 : mkc(1.f, 0.f);
            C2 Wb = (p & 2) ? w2 : mkc(1.f, 0.f);
            W = cmul_s(W, Wb);
            W.x = (p & 4) ? w4.x : W.x;
            W.y = (p & 4) ? w4.y : W.y;
            diag_all(a, W);
        }
        ry_loc_fused<8>(a, (hl & 8) != 0, cs_, ss_, cd_, sd_);
        ry_loc_fused<4>(a, (hl & 4) != 0, cs_, ss_, cd_, sd_);
        ry_loc_fused<2>(a, (hl & 2) != 0, cs_, ss_, cd_, sd_);
        ry_loc_fused<1>(a, (hl & 1) != 0, cs_, ss_, cd_, sd_);
        cx_shfl_id(a);
        mul_i_sel(a, (hl & 8) != 0);

        // ---- parity-1 sweep ----
        xsel_local<8>(a, (hl & 4) != 0);
        xsel_local<4>(a, (hl & 2) != 0);
        xsel_local<2>(a, (hl & 1) != 0);
        zpow<14>(a, w1, w2, w3);
        ry_lane_fxk<4, 8>(a, cs_, ss_, cd_, sd_, hl);
        ry_lane_fxk<2, 4>(a, cs_, ss_, cd_, sd_, hl);
        ry_lane_fxk<1, 2>(a, cs_, ss_, cd_, sd_, hl);
        xsel_local<8>(a, (hl & 4) != 0);
        xsel_local<4>(a, (hl & 2) != 0);
        xsel_local<2>(a, (hl & 1) != 0);
        kdiag<14, 0>(a);

        C2 U00, U01, U10, U11;
        u3m(u3_p, U00, U01, U10, U11);
        g1<1>(a, U00, U01, U10, U11, lane);
        g1<3>(a, U00, U01, U10, U11, lane);
        g1<5>(a, U00, U01, U10, U11, lane);
        g1<7>(a, U00, U01, U10, U11, lane);
    }

    {   // ---- layer 1 (all local) ----
        float zs, zc;
        __sincosf(rz_p[1], &zs, &zc);
        C2 w1 = mkc(zc, zs);
        C2 w2 = cmul_s(w1, w1);
        float yc, ys, y2c, y2s;
        __sincosf(ry_p[1]  * 0.5f, &ys,  &yc);
        __sincosf(ry2_p[1] * 0.5f, &y2s, &y2c);
        const float cs_ = yc*y2c - ys*y2s, ss_ = ys*y2c + yc*y2s;
        const float cd_ = yc*y2c + ys*y2s, sd_ = ys*y2c - yc*y2s;

        kdiag<0, 5>(a);
        cx_local<4, 8>(a);
        cx_local<1, 2>(a);
        zpow<10>(a, w1, w2, w2);
        ry_local_sel_x<8, 4>(a, cs_, ss_, cd_, sd_);
        ry_local_sel_x<2, 1>(a, cs_, ss_, cd_, sd_);
        cx_local<4, 8>(a);
        cx_local<1, 2>(a);
        kdiag<10, 2>(a);

        cx_local<2, 4>(a);
        zpow<4>(a, w1, w2, w2);
        ry_local_sel_x<4, 2>(a, cs_, ss_, cd_, sd_);
        cx_local<2, 4>(a);
        kdiag<4, 0>(a);

        C2 U00, U01, U10, U11;
        u3m(u3_p + 3, U00, U01, U10, U11);
        g1<3>(a, U00, U01, U10, U11, lane);
        g1<7>(a, U00, U01, U10, U11, lane);
    }

    float f0, f1;
    {
        float p3 = 0.f, p7 = 0.f;
        #pragma unroll
        for (int k = 0; k < 16; ++k) {
            float m = fmaf(a[k].x, a[k].x, a[k].y * a[k].y);
            p3 += (k & 4) ? -m : m;
            p7 += (k & 1) ? -m : m;
        }
        f0 = wsum16(p3);
        f1 = wsum16(p7);
    }

    // ================= MLP head =================
    float hv = 0.f;
    if (hl < 15) {
        float z = b1[hl];
        z = fmaf(W1[hl*4+0], f0, z);
        z = fmaf(W1[hl*4+1], f1, z);
        z = fmaf(W1[hl*4+2], f2, z);
        z = fmaf(W1[hl*4+3], f3, z);
        hv = tanhf(z) * W2[hl];
    }
    float s = wsum16(hv);
    if (hl == 0 && elem < B) {
        float zf = s + b2[0];
        out[elem] = 1.0f / (1.0f + __expf(-zf));
    }
}

extern "C" void kernel_launch(void* const* d_in, const int* in_sizes, int n_in,
                              void* d_out, int out_size) {
    const float* x     = (const float*)d_in[0];
    const float* rz_p  = (const float*)d_in[1];
    const float* ry_p  = (const float*)d_in[2];
    const float* ry2_p = (const float*)d_in[3];
    const float* crx_p = (const float*)d_in[4];
    const float* u3_p  = (const float*)d_in[5];
    const float* u3b_p = (const float*)d_in[6];
    const float* W1    = (const float*)d_in[7];
    const float* b1    = (const float*)d_in[8];
    const float* W2    = (const float*)d_in[9];
    const float* b2    = (const float*)d_in[10];

    int B = in_sizes[0] / 32;          // x is (B, 32)
    const int threads = 64;            // 2 warps/block, 4 elements/block
    int blocks = (B + 3) / 4;
    qcnn_kernel<<<blocks, threads>>>(x, rz_p, ry_p, ry2_p, crx_p, u3_p, u3b_p,
                                     W1, b1, W2, b2, (float*)d_out, B);
}

// round 14
// speedup vs baseline: 1.1516x; 1.0099x over previous
#include <cuda_runtime.h>
#include <cuda_bf16.h>

#define FULL 0xffffffffu

struct C2 { float x, y; };
__device__ __forceinline__ C2 mkc(float x, float y){ C2 c; c.x=x; c.y=y; return c; }
#define DUP(s) mkc((s),(s))

// ---------- packed f32x2 elementwise ops ----------
__device__ __forceinline__ C2 pfma(C2 a, C2 b, C2 c){
    C2 r;
    asm("{\n\t.reg .b64 A,B,C,D;\n\t"
        "mov.b64 A,{%2,%3};\n\t"
        "mov.b64 B,{%4,%5};\n\t"
        "mov.b64 C,{%6,%7};\n\t"
        "fma.rn.f32x2 D, A, B, C;\n\t"
        "mov.b64 {%0,%1}, D;\n\t}"
        : "=f"(r.x), "=f"(r.y)
        : "f"(a.x), "f"(a.y), "f"(b.x), "f"(b.y), "f"(c.x), "f"(c.y));
    return r;
}
__device__ __forceinline__ C2 pmul(C2 a, C2 b){
    C2 r;
    asm("{\n\t.reg .b64 A,B,D;\n\t"
        "mov.b64 A,{%2,%3};\n\t"
        "mov.b64 B,{%4,%5};\n\t"
        "mul.rn.f32x2 D, A, B;\n\t"
        "mov.b64 {%0,%1}, D;\n\t}"
        : "=f"(r.x), "=f"(r.y)
        : "f"(a.x), "f"(a.y), "f"(b.x), "f"(b.y));
    return r;
}
__device__ __forceinline__ C2 swapc(C2 v){ return mkc(v.y, v.x); }

// Mapping: 16 amplitudes/thread (k bits 0..3), 16 lanes/element, elem = lane bit 4.
//   odd qubits  (1,3,5,7) -> LOCAL k bits : q7->k1, q5->k2, q3->k4, q1->k8
//   even qubits (0,2,4,6) -> LANE bits    : q6->l1, q4->l2, q2->l4, q0->l8
template<int Q> struct QM {
    static constexpr bool local = (Q & 1) != 0;
    static constexpr int mask = local ? (1 << ((7 - Q) >> 1)) : (1 << ((6 - Q) >> 1));
};

__device__ __forceinline__ constexpr int cpop(int v){
    return (v&1)+((v>>1)&1)+((v>>2)&1)+((v>>3)&1);
}

__device__ __forceinline__ C2 cmul_s(C2 a, C2 b){
    return mkc(a.x*b.x - a.y*b.y, a.x*b.y + a.y*b.x);
}

// multiply a[k] by i^e(k), e(k) = (popc(k&MP) + 3*popc(k&MM)) & 3
template<int MP, int MM>
__device__ __forceinline__ void kdiag(C2 a[16]){
    #pragma unroll
    for (int k = 0; k < 16; ++k){
        const int e = (cpop(k & MP) + 3 * cpop(k & MM)) & 3;
        if (e == 1){ float t = a[k].x; a[k].x = -a[k].y; a[k].y =  t; }
        else if (e == 2){ a[k].x = -a[k].x; a[k].y = -a[k].y; }
        else if (e == 3){ float t = a[k].x; a[k].x =  a[k].y; a[k].y = -t; }
    }
}

// multiply ALL regs by complex W
__device__ __forceinline__ void diag_all(C2 a[16], C2 W){
    C2 P = DUP(W.x), Q = mkc(-W.y, W.y);
    #pragma unroll
    for (int k = 0; k < 16; ++k)
        a[k] = pfma(Q, swapc(a[k]), pmul(P, a[k]));
}

// multiply ALL regs by i where cb — SEL-based, ALU pipe
__device__ __forceinline__ void mul_i_sel(C2 a[16], bool cb){
    #pragma unroll
    for (int k = 0; k < 16; ++k){
        float nx = cb ? -a[k].y : a[k].x;
        float ny = cb ?  a[k].x : a[k].y;
        a[k].x = nx; a[k].y = ny;
    }
}

// multiply a[k] by w1^popc(k&MASK)
template<int MASK>
__device__ __forceinline__ void zpow(C2 a[16], C2 w1, C2 w2, C2 w3){
    #pragma unroll
    for (int k = 0; k < 16; ++k){
        const int p = cpop(k & MASK);
        if (p){
            C2 w = (p == 1) ? w1 : (p == 2) ? w2 : w3;
            a[k] = pfma(mkc(-w.y, w.y), swapc(a[k]), pmul(DUP(w.x), a[k]));
        }
    }
}

// FUSED RY(t1)->CX->RY(t2) on LOCAL target bit M; ctrl = runtime lane-uniform cb.
template<int M>
__device__ __forceinline__ void ry_loc_fused(C2 a[16], bool cb,
        float cs_, float ss_, float cd_, float sd_){
    C2 A0 = DUP(cb ? sd_ : cs_), B0 = DUP(cb ? cd_ : -ss_);
    C2 A1 = DUP(cb ? cd_ : ss_), B1 = DUP(cb ? -sd_ : cs_);
    #pragma unroll
    for (int k0 = 0; k0 < 16; ++k0) if (!(k0 & M)){
        int k1 = k0 | M;
        C2 a0 = a[k0], a1 = a[k1];
        a[k0] = pfma(A0, a0, pmul(B0, a1));
        a[k1] = pfma(A1, a0, pmul(B1, a1));
    }
}

// FUSED RY(t1)->CX->RY(t2) on LANE target bit LM; ctrl = LOCAL k-bit KM.
template<int LM, int KM>
__device__ __forceinline__ void ry_lane_fxk(C2 a[16],
        float cs_, float ss_, float cd_, float sd_, int hl){
    bool hi = (hl & LM) != 0;
    C2 CA0 = DUP(cs_),              CO0 = DUP(hi ? ss_ : -ss_);
    C2 CA1 = DUP(hi ? -sd_ : sd_),  CO1 = DUP(cd_);
    #pragma unroll
    for (int k = 0; k < 16; ++k){
        float px = __shfl_xor_sync(FULL, a[k].x, LM);
        float py = __shfl_xor_sync(FULL, a[k].y, LM);
        C2 p = mkc(px, py);
        if (k & KM) a[k] = pfma(CO1, p, pmul(CA1, a[k]));
        else        a[k] = pfma(CO0, p, pmul(CA0, a[k]));
    }
}

// X on local bit M, conditioned on runtime flag cb
template<int M>
__device__ __forceinline__ void xsel_local(C2 a[16], bool cb){
    #pragma unroll
    for (int k0 = 0; k0 < 16; ++k0) if (!(k0 & M)){
        int k1 = k0 | M;
        C2 t0 = a[k0], t1 = a[k1];
        a[k0] = cb ? t1 : t0;
        a[k1] = cb ? t0 : t1;
    }
}

// merged parity-0 CX stage: a[k] -> shfl_xor(a[k], k)
__device__ __forceinline__ void cx_shfl_id(C2 a[16]){
    #pragma unroll
    for (int k = 1; k < 16; ++k){
        a[k].x = __shfl_xor_sync(FULL, a[k].x, k);
        a[k].y = __shfl_xor_sync(FULL, a[k].y, k);
    }
}

// local RY on bit MT with per-k coeff selected by k&KM, then compile-time X if k&KM
template<int KM, int MT>
__device__ __forceinline__ void ry_local_sel_x(C2 a[16],
        float cs, float ss, float cd, float sd){
    #pragma unroll
    for (int k0 = 0; k0 < 16; ++k0) if (!(k0 & MT)){
        int k1 = k0 | MT;
        const float ce = (k0 & KM) ? cd : cs;
        const float se = (k0 & KM) ? sd : ss;
        C2 a0 = a[k0], a1 = a[k1];
        C2 n0 = pfma(DUP(ce), a0, pmul(DUP(-se), a1));
        C2 n1 = pfma(DUP(se), a0, pmul(DUP(ce), a1));
        if (k0 & KM){ a[k0] = n1; a[k1] = n0; }
        else        { a[k0] = n0; a[k1] = n1; }
    }
}

// compile-time local CX: control bit MC, target bit MT
template<int MC, int MT>
__device__ __forceinline__ void cx_local(C2 a[16]){
    #pragma unroll
    for (int k0 = 0; k0 < 16; ++k0) if ((k0 & MC) && !(k0 & MT)){
        int k1 = k0 | MT; C2 t = a[k0]; a[k0] = a[k1]; a[k1] = t;
    }
}

// ---------------- generic complex 1q gate ----------------
template<int Q>
__device__ __forceinline__ void g1(C2 a[16], C2 u00, C2 u01, C2 u10, C2 u11, int lane){
    constexpr int m = QM<Q>::mask;
    if constexpr (QM<Q>::local) {
        C2 x00 = DUP(u00.x), y00 = mkc(-u00.y, u00.y);
        C2 x01 = DUP(u01.x), y01 = mkc(-u01.y, u01.y);
        C2 x10 = DUP(u10.x), y10 = mkc(-u10.y, u10.y);
        C2 x11 = DUP(u11.x), y11 = mkc(-u11.y, u11.y);
        #pragma unroll
        for (int k0 = 0; k0 < 16; ++k0) if (!(k0 & m)) {
            int k1 = k0 | m;
            C2 a0 = a[k0], a1 = a[k1];
            C2 a0s = swapc(a0), a1s = swapc(a1);
            C2 t0 = pmul(x00, a0); t0 = pfma(y00, a0s, t0);
            t0 = pfma(x01, a1, t0); t0 = pfma(y01, a1s, t0);
            C2 t1 = pmul(x10, a0); t1 = pfma(y10, a0s, t1);
            t1 = pfma(x11, a1, t1); t1 = pfma(y11, a1s, t1);
            a[k0] = t0; a[k1] = t1;
        }
    } else {
        bool hi = (lane & m) != 0;
        C2 xA = hi ? DUP(u11.x) : DUP(u00.x);
        C2 yA = hi ? mkc(-u11.y, u11.y) : mkc(-u00.y, u00.y);
        C2 xB = hi ? DUP(u10.x) : DUP(u01.x);
        C2 yB = hi ? mkc(-u10.y, u10.y) : mkc(-u01.y, u01.y);
        #pragma unroll
        for (int k = 0; k < 16; ++k) {
            float px = __shfl_xor_sync(FULL, a[k].x, m);
            float py = __shfl_xor_sync(FULL, a[k].y, m);
            C2 t = pmul(xA, a[k]); t = pfma(yA, swapc(a[k]), t);
            t = pfma(xB, mkc(px, py), t); t = pfma(yB, mkc(py, px), t);
            a[k] = t;
        }
    }
}

// ---------------- CRX (packed; shuffle value last-in-chain) ----------------
template<int QC, int QT>
__device__ __forceinline__ void gcrx(C2 a[16], float c, float s, int lane){
    constexpr int mc = QM<QC>::mask, mt = QM<QT>::mask;
    if constexpr (QM<QC>::local && QM<QT>::local) {
        C2 c2 = DUP(c), sn = mkc(s, -s);
        #pragma unroll
        for (int k0 = 0; k0 < 16; ++k0) if ((k0 & mc) && !(k0 & mt)) {
            int k1 = k0 | mt;
            C2 a0 = a[k0], a1 = a[k1];
            a[k0] = pfma(c2, a0, pmul(sn, swapc(a1)));
            a[k1] = pfma(c2, a1, pmul(sn, swapc(a0)));
        }
    } else if constexpr (QM<QC>::local) {
        C2 c2 = DUP(c), sn = mkc(s, -s);
        #pragma unroll
        for (int k = 0; k < 16; ++k) if (k & mc) {
            float px = __shfl_xor_sync(FULL, a[k].x, mt);
            float py = __shfl_xor_sync(FULL, a[k].y, mt);
            a[k] = pfma(sn, mkc(py, px), pmul(c2, a[k]));
        }
    } else if constexpr (QM<QT>::local) {
        bool cb = (lane & mc) != 0;
        C2 c2 = DUP(cb ? c : 1.0f);
        C2 sn = cb ? mkc(s, -s) : mkc(0.f, 0.f);
        #pragma unroll
        for (int k0 = 0; k0 < 16; ++k0) if (!(k0 & mt)) {
            int k1 = k0 | mt;
            C2 a0 = a[k0], a1 = a[k1];
            a[k0] = pfma(c2, a0, pmul(sn, swapc(a1)));
            a[k1] = pfma(c2, a1, pmul(sn, swapc(a0)));
        }
    } else {
        bool cb = (lane & mc) != 0;
        C2 c2 = DUP(cb ? c : 1.0f);
        C2 sn = cb ? mkc(s, -s) : mkc(0.f, 0.f);
        #pragma unroll
        for (int k = 0; k < 16; ++k) {
            float px = __shfl_xor_sync(FULL, a[k].x, mt);
            float py = __shfl_xor_sync(FULL, a[k].y, mt);
            a[k] = pfma(sn, mkc(py, px), pmul(c2, a[k]));
        }
    }
}

// ---------------- real-state encode gates ----------------
template<int Q>
__device__ __forceinline__ void gryR(float r[16], float c, float s, int lane){
    constexpr int m = QM<Q>::mask;
    C2 c2 = DUP(c);
    if constexpr (QM<Q>::local) {
        if constexpr (m == 1) {
            C2 snn = mkc(-s, s);
            #pragma unroll
            for (int j = 0; j < 8; ++j) {
                C2 v = mkc(r[2*j], r[2*j+1]);
                C2 res = pfma(snn, swapc(v), pmul(c2, v));
                r[2*j] = res.x; r[2*j+1] = res.y;
            }
        } else {
            constexpr int pm = m >> 1;
            C2 s2 = DUP(s), ns2 = DUP(-s);
            #pragma unroll
            for (int j0 = 0; j0 < 8; ++j0) if (!(j0 & pm)) {
                int j1 = j0 | pm;
                C2 v0 = mkc(r[2*j0], r[2*j0+1]);
                C2 v1 = mkc(r[2*j1], r[2*j1+1]);
                C2 n0 = pfma(c2, v0, pmul(ns2, v1));
                C2 n1 = pfma(s2, v0, pmul(c2, v1));
                r[2*j0] = n0.x; r[2*j0+1] = n0.y;
                r[2*j1] = n1.x; r[2*j1+1] = n1.y;
            }
        }
    } else {
        C2 sg2 = (lane & m) ? DUP(s) : DUP(-s);
        #pragma unroll
        for (int j = 0; j < 8; ++j) {
            float px = __shfl_xor_sync(FULL, r[2*j],   m);
            float py = __shfl_xor_sync(FULL, r[2*j+1], m);
            C2 v = mkc(r[2*j], r[2*j+1]);
            C2 res = pfma(sg2, mkc(px, py), pmul(c2, v));
            r[2*j] = res.x; r[2*j+1] = res.y;
        }
    }
}

template<int QC, int QT>
__device__ __forceinline__ void gcxR(float r[16], int lane){
    constexpr int mc = QM<QC>::mask, mt = QM<QT>::mask;
    if constexpr (QM<QC>::local && QM<QT>::local) {
        #pragma unroll
        for (int k0 = 0; k0 < 16; ++k0) if ((k0 & mc) && !(k0 & mt)) {
            int k1 = k0 | mt; float t = r[k0]; r[k0] = r[k1]; r[k1] = t;
        }
    } else if constexpr (QM<QC>::local) {
        #pragma unroll
        for (int k = 0; k < 16; ++k) if (k & mc)
            r[k] = __shfl_xor_sync(FULL, r[k], mt);
    } else if constexpr (QM<QT>::local) {
        bool cb = (lane & mc) != 0;
        #pragma unroll
        for (int k0 = 0; k0 < 16; ++k0) if (!(k0 & mt)) {
            int k1 = k0 | mt;
            float t0 = r[k0], t1 = r[k1];
            r[k0] = cb ? t1 : t0;
            r[k1] = cb ? t0 : t1;
        }
    } else {
        bool cb = (lane & mc) != 0;
        #pragma unroll
        for (int k = 0; k < 16; ++k) {
            float pv = __shfl_xor_sync(FULL, r[k], mt);
            r[k] = cb ? pv : r[k];
        }
    }
}

__device__ __forceinline__ float wsum16(float v){
    #pragma unroll
    for (int o = 8; o; o >>= 1) v += __shfl_xor_sync(FULL, v, o);
    return v;
}

__device__ __forceinline__ void u3m(const float* p, C2& U00, C2& U01, C2& U10, C2& U11){
    float t = p[0], ph = p[1], la = p[2];
    float st, ct, sp, cp, sl, cl, spl, cpl;
    __sincosf(t * 0.5f, &st, &ct);
    __sincosf(ph, &sp, &cp);
    __sincosf(la, &sl, &cl);
    __sincosf(ph + la, &spl, &cpl);
    U00 = mkc(ct, 0.f);
    U01 = mkc(-cl*st, -sl*st);
    U10 = mkc( cp*st,  sp*st);
    U11 = mkc(cpl*ct, spl*ct);
}

__global__ void __launch_bounds__(64, 10)
qcnn_kernel(const float* __restrict__ x,
            const float* __restrict__ rz_p,  const float* __restrict__ ry_p,
            const float* __restrict__ ry2_p, const float* __restrict__ crx_p,
            const float* __restrict__ u3_p,  const float* __restrict__ u3b_p,
            const float* __restrict__ W1,    const float* __restrict__ b1,
            const float* __restrict__ W2,    const float* __restrict__ b2,
            float* __restrict__ out, int B)
{
    const int warp = (blockIdx.x * blockDim.x + threadIdx.x) >> 5;
    const int lane = threadIdx.x & 31;
    const int hl   = lane & 15;
    const int elem = warp * 2 + (lane >> 4);
    if (warp * 2 >= B) return;
    const int e = (elem < B) ? elem : (B - 1);

    // ================= encode (state purely REAL) =================
    float2 av = reinterpret_cast<const float2*>(x)[e * 16 + hl];
    float c0, s0, c1, s1;
    __sincosf(0.5f * av.x, &s0, &c0);
    __sincosf(0.5f * av.y, &s1, &c1);

    #define GETC(IDX) __shfl_sync(FULL, (((IDX) & 1) ? c1 : c0), (lane & 16) | ((IDX) >> 1))
    #define GETS(IDX) __shfl_sync(FULL, (((IDX) & 1) ? s1 : s0), (lane & 16) | ((IDX) >> 1))

    float r[16];
    {   // cycle 0: direct product state
        float qc[8], qs[8];
        #pragma unroll
        for (int q = 0; q < 8; ++q){ qc[q] = GETC(q); qs[q] = GETS(q); }
        float F = ((hl & 8) ? qs[0] : qc[0]) * ((hl & 4) ? qs[2] : qc[2])
                * ((hl & 2) ? qs[4] : qc[4]) * ((hl & 1) ? qs[6] : qc[6]);
        float u_[4] = { qc[1]*qc[3], qc[1]*qs[3], qs[1]*qc[3], qs[1]*qs[3] };
        float v_[4] = { qc[5]*qc[7], qc[5]*qs[7], qs[5]*qc[7], qs[5]*qs[7] };
        #pragma unroll
        for (int i = 0; i < 4; ++i) u_[i] *= F;
        #pragma unroll
        for (int k = 0; k < 16; ++k) r[k] = u_[k >> 2] * v_[k & 3];
    }

    #define RYQ(CY,Q) do { \
        const int idx_ = (CY)*8 + (Q); \
        float cc_ = GETC(idx_); \
        float ss_ = GETS(idx_); \
        gryR<Q>(r, cc_, ss_, lane); } while(0)

    #define CX_RING() \
        gcxR<0,1>(r,lane); gcxR<1,2>(r,lane); gcxR<2,3>(r,lane); gcxR<3,4>(r,lane); \
        gcxR<4,5>(r,lane); gcxR<5,6>(r,lane); gcxR<6,7>(r,lane); gcxR<7,0>(r,lane);

    #define ENC_CYC(CY) \
        RYQ(CY,0); RYQ(CY,1); RYQ(CY,2); RYQ(CY,3); \
        RYQ(CY,4); RYQ(CY,5); RYQ(CY,6); RYQ(CY,7); \
        CX_RING()

    CX_RING()
    ENC_CYC(1) ENC_CYC(2) ENC_CYC(3)

    // ================= dual-state psi phase: both circuits live at once ======
    C2 A[16], Bs[16];
    #pragma unroll
    for (int k = 0; k < 16; ++k){ A[k] = mkc(r[k], 0.f); Bs[k] = A[k]; }

    // --- psi0 layer-0 parameters ---
    float zs0, zc0;
    __sincosf(rz_p[0], &zs0, &zc0);
    C2 w1 = mkc(zc0, zs0);
    C2 w2 = cmul_s(w1, w1);
    C2 w3 = cmul_s(w2, w1);
    float yc, ys, y2c, y2s;
    __sincosf(ry_p[0]  * 0.5f, &ys,  &yc);
    __sincosf(ry2_p[0] * 0.5f, &y2s, &y2c);
    float cs_ = yc*y2c - ys*y2s, ss_ = ys*y2c + yc*y2s;
    float cd_ = yc*y2c + ys*y2s, sd_ = ys*y2c - yc*y2s;
    C2 Wd;   // merged RZ diag for parity-0
    {
        C2 w4 = cmul_s(w2, w2);
        int p = __popc((unsigned)hl);
        Wd = (p & 1) ? w1 : mkc(1.f, 0.f);
        if (p & 2) Wd = cmul_s(Wd, w2);
        Wd.x = (p & 4) ? w4.x : Wd.x;
        Wd.y = (p & 4) ? w4.y : Wd.y;
    }
    // --- psi1 layer-0 params ---
    float xc0, xs0;
    __sincosf(crx_p[0] * 0.5f, &xs0, &xc0);

    // ====== interleaved chunk 1: psi1-l0 CRX ladder  ||  psi0-l0 parity-0 ======
    gcrx<0,1>(Bs, xc0, xs0, lane);
    gcrx<2,3>(Bs, xc0, xs0, lane);
    gcrx<4,5>(Bs, xc0, xs0, lane);
    gcrx<6,7>(Bs, xc0, xs0, lane);

    kdiag<0, 15>(A);
    cx_shfl_id(A);

    gcrx<1,2>(Bs, xc0, xs0, lane);
    gcrx<3,4>(Bs, xc0, xs0, lane);
    gcrx<5,6>(Bs, xc0, xs0, lane);

    diag_all(A, Wd);
    ry_loc_fused<8>(A, (hl & 8) != 0, cs_, ss_, cd_, sd_);
    ry_loc_fused<4>(A, (hl & 4) != 0, cs_, ss_, cd_, sd_);

    // ====== chunk 2: psi1-l0 U3  ||  psi0-l0 parity-0 tail ======
    {
        C2 U00, U01, U10, U11;
        u3m(u3b_p, U00, U01, U10, U11);
        g1<1>(Bs, U00, U01, U10, U11, lane);
        g1<3>(Bs, U00, U01, U10, U11, lane);

        ry_loc_fused<2>(A, (hl & 2) != 0, cs_, ss_, cd_, sd_);
        ry_loc_fused<1>(A, (hl & 1) != 0, cs_, ss_, cd_, sd_);

        g1<5>(Bs, U00, U01, U10, U11, lane);
        g1<7>(Bs, U00, U01, U10, U11, lane);

        cx_shfl_id(A);
        mul_i_sel(A, (hl & 8) != 0);
    }

    // ====== chunk 3: psi1-l1  ||  psi0-l0 parity-1 ======
    xsel_local<8>(A, (hl & 4) != 0);
    xsel_local<4>(A, (hl & 2) != 0);
    xsel_local<2>(A, (hl & 1) != 0);
    zpow<14>(A, w1, w2, w3);

    {
        float xc1, xs1;
        __sincosf(crx_p[1] * 0.5f, &xs1, &xc1);
        gcrx<1,3>(Bs, xc1, xs1, lane);
        gcrx<5,7>(Bs, xc1, xs1, lane);

        ry_lane_fxk<4, 8>(A, cs_, ss_, cd_, sd_, hl);

        gcrx<3,5>(Bs, xc1, xs1, lane);

        ry_lane_fxk<2, 4>(A, cs_, ss_, cd_, sd_, hl);
    }
    {
        C2 U00, U01, U10, U11;
        u3m(u3b_p + 3, U00, U01, U10, U11);
        g1<3>(Bs, U00, U01, U10, U11, lane);

        ry_lane_fxk<1, 2>(A, cs_, ss_, cd_, sd_, hl);

        g1<7>(Bs, U00, U01, U10, U11, lane);

        xsel_local<8>(A, (hl & 4) != 0);
        xsel_local<4>(A, (hl & 2) != 0);
        xsel_local<2>(A, (hl & 1) != 0);
        kdiag<14, 0>(A);
    }

    // ====== chunk 4: measure psi1  ||  psi0-l0 U3 ======
    float f2, f3;
    {
        float p3 = 0.f, p7 = 0.f;
        #pragma unroll
        for (int k = 0; k < 16; ++k) {
            float m = fmaf(Bs[k].x, Bs[k].x, Bs[k].y * Bs[k].y);
            p3 += (k & 4) ? -m : m;
            p7 += (k & 1) ? -m : m;
        }
        f2 = wsum16(p3);
        f3 = wsum16(p7);
    }
    {
        C2 U00, U01, U10, U11;
        u3m(u3_p, U00, U01, U10, U11);
        g1<1>(A, U00, U01, U10, U11, lane);
        g1<3>(A, U00, U01, U10, U11, lane);
        g1<5>(A, U00, U01, U10, U11, lane);
        g1<7>(A, U00, U01, U10, U11, lane);
    }

    // ====== psi0 layer 1 (all local) ======
    {
        float zs, zc;
        __sincosf(rz_p[1], &zs, &zc);
        C2 v1 = mkc(zc, zs);
        C2 v2 = cmul_s(v1, v1);
        float yc1, ys1, y2c1, y2s1;
        __sincosf(ry_p[1]  * 0.5f, &ys1,  &yc1);
        __sincosf(ry2_p[1] * 0.5f, &y2s1, &y2c1);
        const float cs1 = yc1*y2c1 - ys1*y2s1, ss1 = ys1*y2c1 + yc1*y2s1;
        const float cd1 = yc1*y2c1 + ys1*y2s1, sd1 = ys1*y2c1 - yc1*y2s1;

        kdiag<0, 5>(A);
        cx_local<4, 8>(A);
        cx_local<1, 2>(A);
        zpow<10>(A, v1, v2, v2);
        ry_local_sel_x<8, 4>(A, cs1, ss1, cd1, sd1);
        ry_local_sel_x<2, 1>(A, cs1, ss1, cd1, sd1);
        cx_local<4, 8>(A);
        cx_local<1, 2>(A);
        kdiag<10, 2>(A);

        cx_local<2, 4>(A);
        zpow<4>(A, v1, v2, v2);
        ry_local_sel_x<4, 2>(A, cs1, ss1, cd1, sd1);
        cx_local<2, 4>(A);
        kdiag<4, 0>(A);

        C2 U00, U01, U10, U11;
        u3m(u3_p + 3, U00, U01, U10, U11);
        g1<3>(A, U00, U01, U10, U11, lane);
        g1<7>(A, U00, U01, U10, U11, lane);
    }

    float f0, f1;
    {
        float p3 = 0.f, p7 = 0.f;
        #pragma unroll
        for (int k = 0; k < 16; ++k) {
            float m = fmaf(A[k].x, A[k].x, A[k].y * A[k].y);
            p3 += (k & 4) ? -m : m;
            p7 += (k & 1) ? -m : m;
        }
        f0 = wsum16(p3);
        f1 = wsum16(p7);
    }

    // ================= MLP head =================
    float hv = 0.f;
    if (hl < 15) {
        float z = b1[hl];
        z = fmaf(W1[hl*4+0], f0, z);
        z = fmaf(W1[hl*4+1], f1, z);
        z = fmaf(W1[hl*4+2], f2, z);
        z = fmaf(W1[hl*4+3], f3, z);
        hv = tanhf(z) * W2[hl];
    }
    float s = wsum16(hv);
    if (hl == 0 && elem < B) {
        float zf = s + b2[0];
        out[elem] = 1.0f / (1.0f + __expf(-zf));
    }
}

extern "C" void kernel_launch(void* const* d_in, const int* in_sizes, int n_in,
                              void* d_out, int out_size) {
    const float* x     = (const float*)d_in[0];
    const float* rz_p  = (const float*)d_in[1];
    const float* ry_p  = (const float*)d_in[2];
    const float* ry2_p = (const float*)d_in[3];
    const float* crx_p = (const float*)d_in[4];
    const float* u3_p  = (const float*)d_in[5];
    const float* u3b_p = (const float*)d_in[6];
    const float* W1    = (const float*)d_in[7];
    const float* b1    = (const float*)d_in[8];
    const float* W2    = (const float*)d_in[9];
    const float* b2    = (const float*)d_in[10];

    int B = in_sizes[0] / 32;          // x is (B, 32)
    const int threads = 64;            // 2 warps/block, 4 elements/block
    int blocks = (B + 3) / 4;
    qcnn_kernel<<<blocks, threads>>>(x, rz_p, ry_p, ry2_p, crx_p, u3_p, u3b_p,
                                     W1, b1, W2, b2, (float*)d_out, B);
}